// round 13
// baseline (speedup 1.0000x reference)
#include <cuda_runtime.h>
#include <cuda_bf16.h>
#include <cstdint>
#include <math.h>

typedef __nv_bfloat16 bf16;

// ---------------- dims ----------------
static const int cB  = 8;
static const int cL  = 1152;      // T*W
static const int cD  = 512;
static const int cDI = 1024;
static const int cS  = 64;
static const int cDFF= 2048;
static const int cM  = 9216;      // B*L

// ---------------- fp32 workspaces ----------------
__device__ float g_qkv [cM*1536];
__device__ float g_attn[cM*cD];
__device__ float g_xz  [cM*2*cDI];
__device__ float g_u   [cM*cDI];
__device__ float g_xdbc[cM*160];
__device__ float g_dlt [cM*cDI];
__device__ float g_mmb [cM*cD];
__device__ float g_h   [cM*cD];

// ---------------- bf16 split-2 storage [hi|lo] ----------------
__device__ bf16 gx2   [cM*1024];
__device__ bf16 gao2  [cM*1024];
__device__ bf16 gu2   [cM*2048];
__device__ bf16 gxdbc2[cM*64];
__device__ bf16 gy2   [cM*2048];
__device__ bf16 ghn2  [cM*1024];
__device__ bf16 gff12 [cM*4096];

__device__ bf16 wqkv2[1536*1024];
__device__ bf16 wo2  [512*1024];
__device__ bf16 win2 [2048*1024];
__device__ bf16 wxp2 [160*2048];
__device__ bf16 wdt2 [1024*64];
__device__ bf16 wout2[512*2048];
__device__ bf16 wff12[2048*1024];
__device__ bf16 wff22[512*4096];

// ---------------- streams ----------------
struct StreamHolder {
    cudaStream_t sB;
    cudaEvent_t evRoot, evB;
    StreamHolder(){
        cudaStreamCreateWithFlags(&sB, cudaStreamNonBlocking);
        cudaEventCreateWithFlags(&evRoot, cudaEventDisableTiming);
        cudaEventCreateWithFlags(&evB,   cudaEventDisableTiming);
    }
};
static StreamHolder g_sh;

// ---------------- helpers ----------------
union F4U { float4 f4; unsigned long long l[2]; float f[4]; };
union BU  { __nv_bfloat162 b; uint32_t u; };

__device__ __forceinline__ float softplus_f(float v){
    return fmaxf(v, 0.0f) + log1pf(__expf(-fabsf(v)));
}
__device__ __forceinline__ float gelu_f(float v){
    return 0.5f * v * (1.0f + erff(v * 0.70710678118654752f));
}
__device__ __forceinline__ bf16 hi_bf(float a){ return __float2bfloat16(a); }
__device__ __forceinline__ bf16 lo_bf(float a){
    bf16 h = __float2bfloat16(a);
    return __float2bfloat16(a - __bfloat162float(h));
}
__device__ __forceinline__ __nv_bfloat162 hi2(float a, float b){
    return __floats2bfloat162_rn(a, b);
}
__device__ __forceinline__ __nv_bfloat162 lo2(float a, float b){
    __nv_bfloat162 h = __floats2bfloat162_rn(a, b);
    return __floats2bfloat162_rn(a - __bfloat162float(h.x), b - __bfloat162float(h.y));
}
__device__ __forceinline__ uint32_t hi2u(float a, float b){ BU t; t.b = hi2(a, b); return t.u; }
__device__ __forceinline__ uint32_t lo2u(float a, float b){ BU t; t.b = lo2(a, b); return t.u; }

__device__ __forceinline__ uint32_t smem_u32(const void* p){
    uint32_t a;
    asm("{ .reg .u64 t; cvta.to.shared.u64 t, %1; cvt.u32.u64 %0, t; }" : "=r"(a) : "l"(p));
    return a;
}
__device__ __forceinline__ void cp16(uint32_t dst, const void* src){
    asm volatile("cp.async.cg.shared.global [%0], [%1], 16;" :: "r"(dst), "l"(src));
}
__device__ __forceinline__ void ldsm4(uint32_t &r0, uint32_t &r1, uint32_t &r2, uint32_t &r3, uint32_t addr){
    asm volatile("ldmatrix.sync.aligned.m8n8.x4.shared.b16 {%0,%1,%2,%3}, [%4];"
        : "=r"(r0), "=r"(r1), "=r"(r2), "=r"(r3) : "r"(addr));
}
__device__ __forceinline__ void ldsm4t(uint32_t &r0, uint32_t &r1, uint32_t &r2, uint32_t &r3, uint32_t addr){
    asm volatile("ldmatrix.sync.aligned.m8n8.x4.trans.shared.b16 {%0,%1,%2,%3}, [%4];"
        : "=r"(r0), "=r"(r1), "=r"(r2), "=r"(r3) : "r"(addr));
}
__device__ __forceinline__ void mma16816(float* c, uint32_t a0, uint32_t a1, uint32_t a2, uint32_t a3,
                                         uint32_t b0, uint32_t b1){
    asm volatile("mma.sync.aligned.m16n8k16.row.col.f32.bf16.bf16.f32 "
        "{%0,%1,%2,%3}, {%4,%5,%6,%7}, {%8,%9}, {%0,%1,%2,%3};"
        : "+f"(c[0]), "+f"(c[1]), "+f"(c[2]), "+f"(c[3])
        : "r"(a0), "r"(a1), "r"(a2), "r"(a3), "r"(b0), "r"(b1));
}

// =====================================================================
// split2: fp32 [rows x K] -> bf16 [rows x 2K] = [hi | lo]
// =====================================================================
__global__ __launch_bounds__(256) void split2(
    const float* __restrict__ in, int lda, int K,
    bf16* __restrict__ out, long rows)
{
    const int chunks = K >> 2;
    const long idx = (long)blockIdx.x * 256 + threadIdx.x;
    if (idx >= rows * chunks) return;
    const int row = (int)(idx / chunks);
    const int kc = (int)(idx - (long)row * chunks);
    const int blk = (kc * 8) / K;
    const int within = kc * 8 - blk * K;
    const float* src = in + (size_t)row * lda + within;
    F4U s0, s1; s0.f4 = *(const float4*)src; s1.f4 = *(const float4*)(src + 4);
    __nv_bfloat162 o[4];
    if (blk == 1){
        o[0] = lo2(s0.f[0], s0.f[1]); o[1] = lo2(s0.f[2], s0.f[3]);
        o[2] = lo2(s1.f[0], s1.f[1]); o[3] = lo2(s1.f[2], s1.f[3]);
    } else {
        o[0] = hi2(s0.f[0], s0.f[1]); o[1] = hi2(s0.f[2], s0.f[3]);
        o[2] = hi2(s1.f[0], s1.f[1]); o[3] = hi2(s1.f[2], s1.f[3]);
    }
    *(uint4*)&out[(size_t)row * (2 * K) + kc * 8] = *(uint4*)o;
}

struct WSpec { const float* src; bf16* dst; int K; long rows; long base; };
struct WTab  { WSpec e[10]; };

__global__ __launch_bounds__(256) void split2_wgt_all(WTab tab)
{
    const long idx = (long)blockIdx.x * 256 + threadIdx.x;
    int i = 0;
#pragma unroll
    for (int j = 1; j < 10; j++) if (idx >= tab.e[j].base) i = j;
    const WSpec w = tab.e[i];
    const long local = idx - w.base;
    const int chunks = w.K >> 2;
    if (local >= w.rows * chunks) return;
    const int row = (int)(local / chunks);
    const int kc = (int)(local - (long)row * chunks);
    const int blk = (kc * 8) / w.K;
    const int within = kc * 8 - blk * w.K;
    const float* src = w.src + (size_t)row * w.K + within;
    F4U s0, s1; s0.f4 = *(const float4*)src; s1.f4 = *(const float4*)(src + 4);
    __nv_bfloat162 o[4];
    if (blk == 1){
        o[0] = lo2(s0.f[0], s0.f[1]); o[1] = lo2(s0.f[2], s0.f[3]);
        o[2] = lo2(s1.f[0], s1.f[1]); o[3] = lo2(s1.f[2], s1.f[3]);
    } else {
        o[0] = hi2(s0.f[0], s0.f[1]); o[1] = hi2(s0.f[2], s0.f[3]);
        o[2] = hi2(s1.f[0], s1.f[1]); o[3] = hi2(s1.f[2], s1.f[3]);
    }
    *(uint4*)&w.dst[(size_t)row * (2 * w.K) + kc * 8] = *(uint4*)o;
}

// =====================================================================
// HMMA GEMM (unchanged from R11): 512 thr, 16 warps, CTA 128x128, BK tmpl
// =====================================================================
template<int EPI, bool OUT3, int BK>
__global__ __launch_bounds__(512, 2) void hmma_gemm(
    const bf16* __restrict__ A2, const bf16* __restrict__ W2, int Ka,
    const float* __restrict__ bias, const float* __restrict__ bias_b,
    const float* __restrict__ bias_c, const float* __restrict__ res,
    float* __restrict__ C, bf16* __restrict__ C3, int N)
{
    const int PITCH = 2 * BK + 16;
    const int TB = 256 * PITCH;
    extern __shared__ char smem[];
    const uint32_t sb = smem_u32(smem);
    const int tid = threadIdx.x;
    const int wid = tid >> 5, lane = tid & 31;
    const int bm = blockIdx.y * 128;
    const int bn = blockIdx.x * 128;
    const int wm = wid & 3, wn = wid >> 2;
    const int gpitch = 2 * Ka;

    float acc[2][4][4];
#pragma unroll
    for (int i = 0; i < 2; i++)
#pragma unroll
        for (int j = 0; j < 4; j++)
#pragma unroll
            for (int e = 0; e < 4; e++) acc[i][j][e] = 0.f;

    const int NC = (3 * Ka) / BK;
    const int CPR = BK / 8;
    const int NCHUNK = 256 * CPR;
    const int ACH = 128 * CPR;

    auto load_tile = [&](int ci, uint32_t sbase){
        const int lcbase = ci * BK;
        int acol = lcbase; if (acol >= 2 * Ka) acol -= 2 * Ka;
        int wcol = lcbase; if (wcol >= Ka) wcol -= Ka;
#pragma unroll
        for (int cc = 0; cc < NCHUNK / 512; cc++){
            const int c = tid + cc * 512;
            if (c < ACH){
                const int row = c / CPR, ch = c % CPR;
                cp16(sbase + row * PITCH + ch * 16,
                     &A2[(size_t)(bm + row) * gpitch + acol + ch * 8]);
            } else {
                const int c2 = c - ACH;
                const int row = c2 / CPR, ch = c2 % CPR;
                int br = bn + row; if (br >= N) br = N - 1;
                cp16(sbase + 128 * PITCH + row * PITCH + ch * 16,
                     &W2[(size_t)br * gpitch + wcol + ch * 8]);
            }
        }
        asm volatile("cp.async.commit_group;" ::: "memory");
    };

    load_tile(0, sb);
    if (NC > 1) load_tile(1, sb + TB);

    const uint32_t aOff = (uint32_t)((wm * 32 + (lane & 15)) * PITCH + (lane >> 4) * 16);
    const uint32_t bOff = (uint32_t)(128 * PITCH +
                          (wn * 32 + (lane & 7) + ((lane & 16) ? 8 : 0)) * PITCH +
                          ((lane >> 3) & 1) * 16);

    for (int ci = 0; ci < NC; ci++){
        if (ci + 1 < NC) asm volatile("cp.async.wait_group 1;" ::: "memory");
        else             asm volatile("cp.async.wait_group 0;" ::: "memory");
        __syncthreads();
        if (ci + 2 < NC){
            const int nb = (ci + 2) % 3;
            load_tile(ci + 2, sb + (uint32_t)nb * TB);
        }
        const uint32_t cur = sb + (uint32_t)(ci % 3) * TB;

#pragma unroll
        for (int s = 0; s < BK / 16; s++){
            uint32_t a[2][4];
#pragma unroll
            for (int i = 0; i < 2; i++)
                ldsm4(a[i][0], a[i][1], a[i][2], a[i][3], cur + aOff + i * (16 * PITCH) + s * 32);
            uint32_t b0, b1, b2, b3, b4, b5, b6, b7;
            ldsm4(b0, b1, b2, b3, cur + bOff + s * 32);
            ldsm4(b4, b5, b6, b7, cur + bOff + 16 * PITCH + s * 32);
#pragma unroll
            for (int i = 0; i < 2; i++){
                mma16816(acc[i][0], a[i][0], a[i][1], a[i][2], a[i][3], b0, b1);
                mma16816(acc[i][1], a[i][0], a[i][1], a[i][2], a[i][3], b2, b3);
                mma16816(acc[i][2], a[i][0], a[i][1], a[i][2], a[i][3], b4, b5);
                mma16816(acc[i][3], a[i][0], a[i][1], a[i][2], a[i][3], b6, b7);
            }
        }
    }

    const int t4 = lane >> 2, tp = (lane & 3) * 2;
#pragma unroll
    for (int i = 0; i < 2; i++){
#pragma unroll
        for (int j = 0; j < 4; j++){
            const int col = bn + wn * 32 + j * 8 + tp;
            if (col >= N) continue;
            const int row0 = bm + wm * 32 + i * 16 + t4;
            float v0 = acc[i][j][0], v1 = acc[i][j][1];
            float v2 = acc[i][j][2], v3 = acc[i][j][3];
            if (EPI >= 1 && EPI <= 4){
                const float bb0 = bias[col], bb1 = bias[col + 1];
                v0 += bb0; v1 += bb1; v2 += bb0; v3 += bb1;
            }
            if (EPI == 5){
                const float* bp = (col < 512) ? bias : (col < 1024) ? (bias_b - 512) : (bias_c - 1024);
                const float bb0 = bp[col], bb1 = bp[col + 1];
                v0 += bb0; v1 += bb1; v2 += bb0; v3 += bb1;
            }
            if (EPI == 2){ v0 = softplus_f(v0); v1 = softplus_f(v1); v2 = softplus_f(v2); v3 = softplus_f(v3); }
            if (EPI == 3){ v0 = gelu_f(v0); v1 = gelu_f(v1); v2 = gelu_f(v2); v3 = gelu_f(v3); }
            if (EPI == 4){
                v0 += res[(size_t)row0 * N + col];
                v1 += res[(size_t)row0 * N + col + 1];
                v2 += res[(size_t)(row0 + 8) * N + col];
                v3 += res[(size_t)(row0 + 8) * N + col + 1];
            }
            if (OUT3){
                const size_t r0 = (size_t)row0 * (2 * N), r1 = (size_t)(row0 + 8) * (2 * N);
                *(__nv_bfloat162*)&C3[r0 + col]     = hi2(v0, v1);
                *(__nv_bfloat162*)&C3[r0 + N + col] = lo2(v0, v1);
                *(__nv_bfloat162*)&C3[r1 + col]     = hi2(v2, v3);
                *(__nv_bfloat162*)&C3[r1 + N + col] = lo2(v2, v3);
            } else {
                *(float2*)&C[(size_t)row0 * N + col]       = make_float2(v0, v1);
                *(float2*)&C[(size_t)(row0 + 8) * N + col] = make_float2(v2, v3);
            }
        }
    }
}
#define GEMM_SMEM32 (3 * 256 * 80)
#define GEMM_SMEM64 (3 * 256 * 144)

// =====================================================================
// Flash attention v2 (unchanged from R10/R11)
// =====================================================================
#define FQ 0
#define FK 34816
#define FV 52224
#define FMSK 70656
#define FLASH_SMEM 70912

__global__ __launch_bounds__(256, 2) void flash_mma(
    const float* __restrict__ QKV, const unsigned char* __restrict__ mask,
    bf16* __restrict__ AO2)
{
    extern __shared__ char sm[];
    const uint32_t sb = smem_u32(sm);
    float* mskf = (float*)(sm + FMSK);
    const int tid = threadIdx.x;
    const int w = tid >> 5, lane = tid & 31;
    const int t4 = lane >> 2, qq = lane & 3;
    const int bh = blockIdx.y, b = bh >> 3, h = bh & 7;
    const int q0 = blockIdx.x * 128;
    const size_t basebl = (size_t)b * cL;

    for (int idx = tid; idx < 2048; idx += 256){
        const int row = idx >> 4, c4 = idx & 15;
        F4U qv; qv.f4 = *(const float4*)&QKV[(basebl + q0 + row) * 1536 + h * 64 + c4 * 4];
        char* p = sm + FQ + row * 272 + c4 * 8;
        *(__nv_bfloat162*)(p)       = hi2(qv.f[0], qv.f[1]);
        *(__nv_bfloat162*)(p + 4)   = hi2(qv.f[2], qv.f[3]);
        *(__nv_bfloat162*)(p + 128) = lo2(qv.f[0], qv.f[1]);
        *(__nv_bfloat162*)(p + 132) = lo2(qv.f[2], qv.f[3]);
    }

    float m0 = -1e30f, m1 = -1e30f, l0 = 0.f, l1 = 0.f;
    float o[8][4];
#pragma unroll
    for (int nt = 0; nt < 8; nt++)
#pragma unroll
        for (int e = 0; e < 4; e++) o[nt][e] = 0.f;

    for (int jt = 0; jt < cL / 64; jt++){
        __syncthreads();
        for (int idx = tid; idx < 1024; idx += 256){
            const int row = idx >> 4, c4 = idx & 15;
            const size_t gr = (basebl + jt * 64 + row) * 1536 + h * 64 + c4 * 4;
            F4U kv; kv.f4 = *(const float4*)&QKV[gr + 512];
            F4U vv; vv.f4 = *(const float4*)&QKV[gr + 1024];
            char* pk = sm + FK + row * 272 + c4 * 8;
            *(__nv_bfloat162*)(pk)       = hi2(kv.f[0], kv.f[1]);
            *(__nv_bfloat162*)(pk + 4)   = hi2(kv.f[2], kv.f[3]);
            *(__nv_bfloat162*)(pk + 128) = lo2(kv.f[0], kv.f[1]);
            *(__nv_bfloat162*)(pk + 132) = lo2(kv.f[2], kv.f[3]);
            char* ph = sm + FV + row * 144 + c4 * 8;
            *(__nv_bfloat162*)(ph)     = hi2(vv.f[0], vv.f[1]);
            *(__nv_bfloat162*)(ph + 4) = hi2(vv.f[2], vv.f[3]);
            char* pl = sm + FV + (64 + row) * 144 + c4 * 8;
            *(__nv_bfloat162*)(pl)     = lo2(vv.f[0], vv.f[1]);
            *(__nv_bfloat162*)(pl + 4) = lo2(vv.f[2], vv.f[3]);
        }
        if (tid < 64) mskf[tid] = mask[b * cL + jt * 64 + tid] ? -1e30f : 0.0f;
        __syncthreads();

        float sacc[8][4];
#pragma unroll
        for (int nt = 0; nt < 8; nt++)
#pragma unroll
            for (int e = 0; e < 4; e++) sacc[nt][e] = 0.f;

#pragma unroll
        for (int s = 0; s < 12; s++){
            const int ab = (s < 4) ? s * 32 : (s < 8) ? 128 + (s - 4) * 32 : (s - 8) * 32;
            const int bb = (s < 8) ? (s & 3) * 32 : 128 + (s - 8) * 32;
            uint32_t a0, a1, a2, a3;
            ldsm4(a0, a1, a2, a3, sb + FQ + (w * 16 + (lane & 15)) * 272 + ab + (lane >> 4) * 16);
#pragma unroll
            for (int kc = 0; kc < 4; kc++){
                uint32_t b0, b1, b2, b3;
                ldsm4(b0, b1, b2, b3,
                      sb + FK + (kc * 16 + (lane & 7) + ((lane & 16) ? 8 : 0)) * 272 + bb + ((lane >> 3) & 1) * 16);
                mma16816(sacc[2 * kc],     a0, a1, a2, a3, b0, b1);
                mma16816(sacc[2 * kc + 1], a0, a1, a2, a3, b2, b3);
            }
        }

        float mx0 = -1e30f, mx1 = -1e30f;
#pragma unroll
        for (int nt = 0; nt < 8; nt++){
            const float2 mk = *(const float2*)&mskf[nt * 8 + qq * 2];
            sacc[nt][0] = sacc[nt][0] * 0.125f + mk.x;
            sacc[nt][1] = sacc[nt][1] * 0.125f + mk.y;
            sacc[nt][2] = sacc[nt][2] * 0.125f + mk.x;
            sacc[nt][3] = sacc[nt][3] * 0.125f + mk.y;
            mx0 = fmaxf(mx0, fmaxf(sacc[nt][0], sacc[nt][1]));
            mx1 = fmaxf(mx1, fmaxf(sacc[nt][2], sacc[nt][3]));
        }
        mx0 = fmaxf(mx0, __shfl_xor_sync(0xffffffffu, mx0, 1));
        mx0 = fmaxf(mx0, __shfl_xor_sync(0xffffffffu, mx0, 2));
        mx1 = fmaxf(mx1, __shfl_xor_sync(0xffffffffu, mx1, 1));
        mx1 = fmaxf(mx1, __shfl_xor_sync(0xffffffffu, mx1, 2));
        const float mn0 = fmaxf(m0, mx0), mn1 = fmaxf(m1, mx1);
        const float fac0 = __expf(m0 - mn0), fac1 = __expf(m1 - mn1);
        m0 = mn0; m1 = mn1;
        float sum0 = 0.f, sum1 = 0.f;
#pragma unroll
        for (int nt = 0; nt < 8; nt++){
            sacc[nt][0] = __expf(sacc[nt][0] - mn0);
            sacc[nt][1] = __expf(sacc[nt][1] - mn0);
            sacc[nt][2] = __expf(sacc[nt][2] - mn1);
            sacc[nt][3] = __expf(sacc[nt][3] - mn1);
            sum0 += sacc[nt][0] + sacc[nt][1];
            sum1 += sacc[nt][2] + sacc[nt][3];
        }
        sum0 += __shfl_xor_sync(0xffffffffu, sum0, 1);
        sum0 += __shfl_xor_sync(0xffffffffu, sum0, 2);
        sum1 += __shfl_xor_sync(0xffffffffu, sum1, 1);
        sum1 += __shfl_xor_sync(0xffffffffu, sum1, 2);
        l0 = l0 * fac0 + sum0;
        l1 = l1 * fac1 + sum1;
#pragma unroll
        for (int nt = 0; nt < 8; nt++){
            o[nt][0] *= fac0; o[nt][1] *= fac0;
            o[nt][2] *= fac1; o[nt][3] *= fac1;
        }

        uint32_t Ph[4][4], Pl[4][4];
#pragma unroll
        for (int kk = 0; kk < 4; kk++){
            Ph[kk][0] = hi2u(sacc[2*kk][0],   sacc[2*kk][1]);
            Ph[kk][1] = hi2u(sacc[2*kk][2],   sacc[2*kk][3]);
            Ph[kk][2] = hi2u(sacc[2*kk+1][0], sacc[2*kk+1][1]);
            Ph[kk][3] = hi2u(sacc[2*kk+1][2], sacc[2*kk+1][3]);
            Pl[kk][0] = lo2u(sacc[2*kk][0],   sacc[2*kk][1]);
            Pl[kk][1] = lo2u(sacc[2*kk][2],   sacc[2*kk][3]);
            Pl[kk][2] = lo2u(sacc[2*kk+1][0], sacc[2*kk+1][1]);
            Pl[kk][3] = lo2u(sacc[2*kk+1][2], sacc[2*kk+1][3]);
        }

#pragma unroll
        for (int s = 0; s < 12; s++){
            const uint32_t* af = (s < 4) ? Ph[s] : (s < 8) ? Pl[s - 4] : Ph[s - 8];
            const int vr = (s < 8) ? (s & 3) * 16 : 64 + (s - 8) * 16;
#pragma unroll
            for (int nb = 0; nb < 4; nb++){
                uint32_t v0, v1, v2, v3;
                ldsm4t(v0, v1, v2, v3,
                       sb + FV + (vr + (lane & 15)) * 144 + (nb * 16 + ((lane & 16) ? 8 : 0)) * 2);
                mma16816(o[2 * nb],     af[0], af[1], af[2], af[3], v0, v1);
                mma16816(o[2 * nb + 1], af[0], af[1], af[2], af[3], v2, v3);
            }
        }
    }

    const float i0 = 1.0f / l0, i1 = 1.0f / l1;
    const size_t gA = (basebl + q0 + w * 16 + t4) * 1024;
    const size_t gB = gA + 8 * 1024;
#pragma unroll
    for (int nt = 0; nt < 8; nt++){
        const float a0 = o[nt][0] * i0, a1 = o[nt][1] * i0;
        const float a2 = o[nt][2] * i1, a3 = o[nt][3] * i1;
        const int col = h * 64 + nt * 8 + qq * 2;
        *(__nv_bfloat162*)&AO2[gA + col]       = hi2(a0, a1);
        *(__nv_bfloat162*)&AO2[gA + 512 + col] = lo2(a0, a1);
        *(__nv_bfloat162*)&AO2[gB + col]       = hi2(a2, a3);
        *(__nv_bfloat162*)&AO2[gB + 512 + col] = lo2(a2, a3);
    }
}

// =====================================================================
// Depthwise causal conv (KC=4) + SiLU; float4; writes u + u2 [hi|lo]
// =====================================================================
__global__ __launch_bounds__(256) void conv_silu(
    const float* __restrict__ xz, const float* __restrict__ cw,
    const float* __restrict__ cb, float* __restrict__ u, bf16* __restrict__ u2)
{
    const long idx = (long)blockIdx.x * 256 + threadIdx.x;
    const int c = (int)(idx & 255) * 4;
    const int m = (int)(idx >> 8);
    const int b = m / cL, l = m % cL;
    F4U acc; acc.f4 = *(const float4*)&cb[c];
    F4U w0, w1, w2, w3;
    w0.f4 = *(const float4*)&cw[c * 4];
    w1.f4 = *(const float4*)&cw[(c + 1) * 4];
    w2.f4 = *(const float4*)&cw[(c + 2) * 4];
    w3.f4 = *(const float4*)&cw[(c + 3) * 4];
#pragma unroll
    for (int k = 0; k < 4; k++){
        const int ls = l + k - 3;
        if (ls >= 0){
            F4U xv; xv.f4 = *(const float4*)&xz[(size_t)(b * cL + ls) * (2 * cDI) + c];
            acc.f[0] += xv.f[0] * w0.f[k];
            acc.f[1] += xv.f[1] * w1.f[k];
            acc.f[2] += xv.f[2] * w2.f[k];
            acc.f[3] += xv.f[3] * w3.f[k];
        }
    }
#pragma unroll
    for (int e = 0; e < 4; e++) acc.f[e] = acc.f[e] / (1.0f + __expf(-acc.f[e]));
    *(float4*)&u[(size_t)m * cDI + c] = acc.f4;
    const size_t r2 = (size_t)m * 2048;
    __nv_bfloat162 hh[2] = { hi2(acc.f[0], acc.f[1]), hi2(acc.f[2], acc.f[3]) };
    __nv_bfloat162 ll[2] = { lo2(acc.f[0], acc.f[1]), lo2(acc.f[2], acc.f[3]) };
    *(uint2*)&u2[r2 + c]        = *(uint2*)hh;
    *(uint2*)&u2[r2 + 1024 + c] = *(uint2*)ll;
}

// =====================================================================
// Selective scan v3: block = 512 thr = 16 warps = 32 d, per-b.
// B/C/dt/u/z staged to smem via cp.async (double buffer, 1 sync/step).
// Warp: 2 d (16 lanes x 4 states). Grid (DI/32, B).
// smem layout per buf (224 floats): B[64] C[64] dt[32] u[32] z[32]
// =====================================================================
__global__ __launch_bounds__(512) void mamba_scan(
    const float* __restrict__ delta, const float* __restrict__ u,
    const float* __restrict__ xdbc, const float* __restrict__ xz,
    const float* __restrict__ A_log, const float* __restrict__ Dssm,
    bf16* __restrict__ y2)
{
    __shared__ float sbuf[2][224];
    const int tid = threadIdx.x;
    const int warp = tid >> 5, lane = tid & 31;
    const int half = lane >> 4, sl = lane & 15;
    const int d0 = blockIdx.x * 32;
    const int dl = warp * 2 + half;
    const int d = d0 + dl;
    const int b = blockIdx.y;
    float a[4], hh[4];
#pragma unroll
    for (int k = 0; k < 4; k++){
        a[k] = -__expf(A_log[d * cS + sl * 4 + k]);
        hh[k] = 0.f;
    }
    const float Dd = Dssm[d];
    const size_t base = (size_t)b * cL;
    const uint32_t sbase = smem_u32(sbuf);

    auto stage = [&](int t, int buf){
        if (tid < 56){
            const size_t m = base + t;
            const uint32_t dst = sbase + (uint32_t)buf * 896 + tid * 16;
            const float* src;
            if (tid < 32)       src = &xdbc[m * 160 + 32 + tid * 4];
            else if (tid < 40)  src = &delta[m * cDI + d0 + (tid - 32) * 4];
            else if (tid < 48)  src = &u[m * cDI + d0 + (tid - 40) * 4];
            else                src = &xz[m * (2 * cDI) + cDI + d0 + (tid - 48) * 4];
            cp16(dst, src);
        }
        asm volatile("cp.async.commit_group;" ::: "memory");
    };

    stage(0, 0);
    asm volatile("cp.async.wait_group 0;" ::: "memory");
    __syncthreads();

    for (int t = 0; t < cL; t++){
        if (t + 1 < cL) stage(t + 1, (t + 1) & 1);
        const float* bf = sbuf[t & 1];
        const float dt = bf[128 + dl];
        const float uu = bf[160 + dl];
        F4U Bv, Cv;
        Bv.f4 = *(const float4*)&bf[sl * 4];
        Cv.f4 = *(const float4*)&bf[64 + sl * 4];
        const float du = dt * uu;
        float p = 0.f;
#pragma unroll
        for (int k = 0; k < 4; k++){
            hh[k] = hh[k] * __expf(dt * a[k]) + du * Bv.f[k];
            p += hh[k] * Cv.f[k];
        }
        p += __shfl_xor_sync(0xffffffffu, p, 8);
        p += __shfl_xor_sync(0xffffffffu, p, 4);
        p += __shfl_xor_sync(0xffffffffu, p, 2);
        p += __shfl_xor_sync(0xffffffffu, p, 1);
        if (sl == 0){
            const float z = bf[192 + dl];
            float yv = p + uu * Dd;
            yv *= z / (1.0f + __expf(-z));
            const size_t r2 = (base + t) * 2048;
            y2[r2 + d]        = hi_bf(yv);
            y2[r2 + 1024 + d] = lo_bf(yv);
        }
        asm volatile("cp.async.wait_group 0;" ::: "memory");
        __syncthreads();
    }
}

// =====================================================================
// Fused residual + LN1 + LN2; writes h (fp32) and hn2 [hi|lo]
// =====================================================================
__device__ __forceinline__ float blockSum256(float v, float* red){
#pragma unroll
    for (int off = 16; off > 0; off >>= 1) v += __shfl_xor_sync(0xffffffffu, v, off);
    if ((threadIdx.x & 31) == 0) red[threadIdx.x >> 5] = v;
    __syncthreads();
    const float s = red[0]+red[1]+red[2]+red[3]+red[4]+red[5]+red[6]+red[7];
    __syncthreads();
    return s;
}

__global__ __launch_bounds__(256) void ln_fuse(
    const float* __restrict__ xf, const float* __restrict__ attn, const float* __restrict__ mamba,
    const float* __restrict__ g1, const float* __restrict__ b1,
    const float* __restrict__ g2, const float* __restrict__ b2,
    float* __restrict__ h, bf16* __restrict__ hn2)
{
    __shared__ float red[8];
    const size_t m = blockIdx.x;
    const int t = threadIdx.x * 2;
    const size_t r = m * cD;
    const float2 xv = *(const float2*)&xf[r + t];
    const float2 av = *(const float2*)&attn[r + t];
    const float2 mv = *(const float2*)&mamba[r + t];
    float v0 = xv.x + av.x + mv.x;
    float v1 = xv.y + av.y + mv.y;

    const float mean = blockSum256(v0 + v1, red) * (1.0f / cD);
    const float d0 = v0 - mean, d1 = v1 - mean;
    const float var = blockSum256(d0 * d0 + d1 * d1, red) * (1.0f / cD);
    const float inv = rsqrtf(var + 1e-5f);
    const float2 g1v = *(const float2*)&g1[t];
    const float2 b1v = *(const float2*)&b1[t];
    const float h0 = d0 * inv * g1v.x + b1v.x;
    const float h1 = d1 * inv * g1v.y + b1v.y;
    *(float2*)&h[r + t] = make_float2(h0, h1);

    const float mean2 = blockSum256(h0 + h1, red) * (1.0f / cD);
    const float e0 = h0 - mean2, e1 = h1 - mean2;
    const float var2 = blockSum256(e0 * e0 + e1 * e1, red) * (1.0f / cD);
    const float inv2 = rsqrtf(var2 + 1e-6f);
    const float2 g2v = *(const float2*)&g2[t];
    const float2 b2v = *(const float2*)&b2[t];
    const float n0 = e0 * inv2 * g2v.x + b2v.x;
    const float n1 = e1 * inv2 * g2v.y + b2v.y;
    const size_t r2 = m * 1024;
    *(__nv_bfloat162*)&hn2[r2 + t]       = hi2(n0, n1);
    *(__nv_bfloat162*)&hn2[r2 + 512 + t] = lo2(n0, n1);
}

// =====================================================================
// Launch
// =====================================================================
static inline int sgrid2(long rows, int K){
    return (int)((rows * (K >> 2) + 255) / 256);
}

extern "C" void kernel_launch(void* const* d_in, const int* in_sizes, int n_in,
                              void* d_out, int out_size)
{
    (void)in_sizes; (void)n_in; (void)out_size;
    const float* x      = (const float*)d_in[0];
    const unsigned char* mask = (const unsigned char*)d_in[1];
    const float* Wq = (const float*)d_in[2];  const float* bq = (const float*)d_in[3];
    const float* Wk = (const float*)d_in[4];  const float* bk = (const float*)d_in[5];
    const float* Wv = (const float*)d_in[6];  const float* bv = (const float*)d_in[7];
    const float* Wo = (const float*)d_in[8];  const float* bo = (const float*)d_in[9];
    const float* in_w   = (const float*)d_in[10];
    const float* conv_w = (const float*)d_in[11];
    const float* conv_b = (const float*)d_in[12];
    const float* xproj_w= (const float*)d_in[13];
    const float* dt_w   = (const float*)d_in[14];
    const float* dt_b   = (const float*)d_in[15];
    const float* A_log  = (const float*)d_in[16];
    const float* Dssm   = (const float*)d_in[17];
    const float* outp_w = (const float*)d_in[18];
    const float* ln1g   = (const float*)d_in[19];
    const float* ln1b   = (const float*)d_in[20];
    const float* fw1    = (const float*)d_in[21];
    const float* fb1    = (const float*)d_in[22];
    const float* fw2    = (const float*)d_in[23];
    const float* fb2    = (const float*)d_in[24];
    const float* ln2g   = (const float*)d_in[25];
    const float* ln2b   = (const float*)d_in[26];
    float* out = (float*)d_out;

    float *qkv,*attn,*xz,*u,*xdbc,*dlt,*mmb,*h;
    cudaGetSymbolAddress((void**)&qkv,  g_qkv);
    cudaGetSymbolAddress((void**)&attn, g_attn);
    cudaGetSymbolAddress((void**)&xz,   g_xz);
    cudaGetSymbolAddress((void**)&u,    g_u);
    cudaGetSymbolAddress((void**)&xdbc, g_xdbc);
    cudaGetSymbolAddress((void**)&dlt,  g_dlt);
    cudaGetSymbolAddress((void**)&mmb,  g_mmb);
    cudaGetSymbolAddress((void**)&h,    g_h);

    bf16 *px2,*pao2,*pu2,*pxdbc2,*py2,*phn2,*pff12;
    bf16 *pwqkv,*pwo,*pwin,*pwxp,*pwdt,*pwout,*pwf1,*pwf2;
    cudaGetSymbolAddress((void**)&px2,   gx2);
    cudaGetSymbolAddress((void**)&pao2,  gao2);
    cudaGetSymbolAddress((void**)&pu2,   gu2);
    cudaGetSymbolAddress((void**)&pxdbc2,gxdbc2);
    cudaGetSymbolAddress((void**)&py2,   gy2);
    cudaGetSymbolAddress((void**)&phn2,  ghn2);
    cudaGetSymbolAddress((void**)&pff12, gff12);
    cudaGetSymbolAddress((void**)&pwqkv, wqkv2);
    cudaGetSymbolAddress((void**)&pwo,   wo2);
    cudaGetSymbolAddress((void**)&pwin,  win2);
    cudaGetSymbolAddress((void**)&pwxp,  wxp2);
    cudaGetSymbolAddress((void**)&pwdt,  wdt2);
    cudaGetSymbolAddress((void**)&pwout, wout2);
    cudaGetSymbolAddress((void**)&pwf1,  wff12);
    cudaGetSymbolAddress((void**)&pwf2,  wff22);

    cudaFuncSetAttribute(flash_mma, cudaFuncAttributeMaxDynamicSharedMemorySize, FLASH_SMEM);
    cudaFuncSetAttribute(hmma_gemm<0,false,64>, cudaFuncAttributeMaxDynamicSharedMemorySize, GEMM_SMEM64);
    cudaFuncSetAttribute(hmma_gemm<1,false,64>, cudaFuncAttributeMaxDynamicSharedMemorySize, GEMM_SMEM64);
    cudaFuncSetAttribute(hmma_gemm<3,true,64>,  cudaFuncAttributeMaxDynamicSharedMemorySize, GEMM_SMEM64);
    cudaFuncSetAttribute(hmma_gemm<4,false,64>, cudaFuncAttributeMaxDynamicSharedMemorySize, GEMM_SMEM64);
    cudaFuncSetAttribute(hmma_gemm<5,false,64>, cudaFuncAttributeMaxDynamicSharedMemorySize, GEMM_SMEM64);
    cudaFuncSetAttribute(hmma_gemm<2,false,32>, cudaFuncAttributeMaxDynamicSharedMemorySize, GEMM_SMEM32);

    // ---- fused weight-split table ----
    WTab tab;
    long base = 0;
    auto add = [&](int i, const float* src, bf16* dst, int K, long rows){
        tab.e[i] = {src, dst, K, rows, base};
        base += rows * (K >> 2);
    };
    add(0, Wq,      pwqkv,               512,  512);
    add(1, Wk,      pwqkv + 512 * 1024,  512,  512);
    add(2, Wv,      pwqkv + 1024 * 1024, 512,  512);
    add(3, Wo,      pwo,                 512,  512);
    add(4, in_w,    pwin,                512,  2048);
    add(5, xproj_w, pwxp,                1024, 160);
    add(6, dt_w,    pwdt,                32,   1024);
    add(7, outp_w,  pwout,               1024, 512);
    add(8, fw1,     pwf1,                512,  2048);
    add(9, fw2,     pwf2,                2048, 512);
    const int wgrid = (int)((base + 255) / 256);

    cudaStream_t s0 = 0, sB = g_sh.sB;

    // slot 0, 1
    split2_wgt_all<<<wgrid, 256, 0, s0>>>(tab);
    split2<<<sgrid2(cM, 512), 256, 0, s0>>>(x, 512, 512, px2, cM);

    cudaEventRecord(g_sh.evRoot, s0);
    cudaStreamWaitEvent(sB, g_sh.evRoot, 0);

    // mamba branch submitted first (slot 2 = in_proj, slot 3 = conv_silu: ncu target)
    hmma_gemm<0,false,64><<<dim3(16, 72), 512, GEMM_SMEM64, sB>>>(px2, pwin, 512, nullptr, nullptr, nullptr, nullptr, xz, nullptr, 2048);
    conv_silu<<<(cM * 256) / 256, 256, 0, sB>>>(xz, conv_w, conv_b, u, pu2);
    hmma_gemm<0,false,64><<<dim3(2, 72), 512, GEMM_SMEM64, sB>>>(pu2, pwxp, 1024, nullptr, nullptr, nullptr, nullptr, xdbc, nullptr, 160);
    split2<<<sgrid2(cM, 32), 256, 0, sB>>>(xdbc, 160, 32, pxdbc2, cM);
    hmma_gemm<2,false,32><<<dim3(8, 72), 512, GEMM_SMEM32, sB>>>(pxdbc2, pwdt, 32, dt_b, nullptr, nullptr, nullptr, dlt, nullptr, 1024);
    mamba_scan<<<dim3(cDI / 32, cB), 512, 0, sB>>>(dlt, u, xdbc, xz, A_log, Dssm, py2);
    hmma_gemm<0,false,64><<<dim3(4, 72), 512, GEMM_SMEM64, sB>>>(py2, pwout, 1024, nullptr, nullptr, nullptr, nullptr, mmb, nullptr, 512);
    cudaEventRecord(g_sh.evB, sB);

    // attention branch on s0 (runs concurrently with sB)
    hmma_gemm<5,false,64><<<dim3(12, 72), 512, GEMM_SMEM64, s0>>>(px2, pwqkv, 512, bq, bk, bv, nullptr, qkv, nullptr, 1536);
    flash_mma<<<dim3(cL / 128, cB * 8), 256, FLASH_SMEM, s0>>>(qkv, mask, pao2);
    hmma_gemm<1,false,64><<<dim3(4, 72), 512, GEMM_SMEM64, s0>>>(pao2, pwo, 512, bo, nullptr, nullptr, nullptr, attn, nullptr, 512);

    cudaStreamWaitEvent(s0, g_sh.evB, 0);
    ln_fuse<<<cM, 256, 0, s0>>>(x, attn, mmb, ln1g, ln1b, ln2g, ln2b, h, phn2);
    hmma_gemm<3,true,64><<<dim3(16, 72), 512, GEMM_SMEM64, s0>>>(phn2, pwf1, 512, fb1, nullptr, nullptr, nullptr, nullptr, pff12, 2048);
    hmma_gemm<4,false,64><<<dim3(4, 72), 512, GEMM_SMEM64, s0>>>(pff12, pwf2, 2048, fb2, nullptr, nullptr, h, out, nullptr, 512);
}

// round 14
// speedup vs baseline: 1.1671x; 1.1671x over previous
#include <cuda_runtime.h>
#include <cuda_bf16.h>
#include <cstdint>
#include <math.h>

typedef __nv_bfloat16 bf16;

// ---------------- dims ----------------
static const int cB  = 8;
static const int cL  = 1152;      // T*W
static const int cD  = 512;
static const int cDI = 1024;
static const int cS  = 64;
static const int cDFF= 2048;
static const int cM  = 9216;      // B*L

// ---------------- fp32 workspaces ----------------
__device__ float g_qkv [cM*1536];
__device__ float g_attn[cM*cD];
__device__ float g_xz  [cM*2*cDI];
__device__ float g_u   [cM*cDI];
__device__ float g_xdbc[cM*160];
__device__ float g_dlt [cM*cDI];
__device__ float g_mmb [cM*cD];
__device__ float g_h   [cM*cD];

// ---------------- bf16 split-2 storage [hi|lo] ----------------
__device__ bf16 gx2   [cM*1024];
__device__ bf16 gao2  [cM*1024];
__device__ bf16 gu2   [cM*2048];
__device__ bf16 gxdbc2[cM*64];
__device__ bf16 gy2   [cM*2048];
__device__ bf16 ghn2  [cM*1024];
__device__ bf16 gff12 [cM*4096];

__device__ bf16 wqi2 [3584*1024];   // QKV rows 0-1535, in_proj rows 1536-3583
__device__ bf16 wo2  [512*1024];
__device__ bf16 wxp2 [160*2048];
__device__ bf16 wdt2 [1024*64];
__device__ bf16 wout2[512*2048];
__device__ bf16 wff12[2048*1024];
__device__ bf16 wff22[512*4096];

// ---------------- streams ----------------
struct StreamHolder {
    cudaStream_t sB;
    cudaEvent_t evRoot, evB;
    StreamHolder(){
        cudaStreamCreateWithFlags(&sB, cudaStreamNonBlocking);
        cudaEventCreateWithFlags(&evRoot, cudaEventDisableTiming);
        cudaEventCreateWithFlags(&evB,   cudaEventDisableTiming);
    }
};
static StreamHolder g_sh;

// ---------------- helpers ----------------
union F4U { float4 f4; unsigned long long l[2]; float f[4]; };
union BU  { __nv_bfloat162 b; uint32_t u; };

__device__ __forceinline__ float softplus_f(float v){
    return fmaxf(v, 0.0f) + log1pf(__expf(-fabsf(v)));
}
__device__ __forceinline__ float gelu_f(float v){
    return 0.5f * v * (1.0f + erff(v * 0.70710678118654752f));
}
__device__ __forceinline__ bf16 hi_bf(float a){ return __float2bfloat16(a); }
__device__ __forceinline__ bf16 lo_bf(float a){
    bf16 h = __float2bfloat16(a);
    return __float2bfloat16(a - __bfloat162float(h));
}
__device__ __forceinline__ __nv_bfloat162 hi2(float a, float b){
    return __floats2bfloat162_rn(a, b);
}
__device__ __forceinline__ __nv_bfloat162 lo2(float a, float b){
    __nv_bfloat162 h = __floats2bfloat162_rn(a, b);
    return __floats2bfloat162_rn(a - __bfloat162float(h.x), b - __bfloat162float(h.y));
}
__device__ __forceinline__ uint32_t hi2u(float a, float b){ BU t; t.b = hi2(a, b); return t.u; }
__device__ __forceinline__ uint32_t lo2u(float a, float b){ BU t; t.b = lo2(a, b); return t.u; }

__device__ __forceinline__ uint32_t smem_u32(const void* p){
    uint32_t a;
    asm("{ .reg .u64 t; cvta.to.shared.u64 t, %1; cvt.u32.u64 %0, t; }" : "=r"(a) : "l"(p));
    return a;
}
__device__ __forceinline__ void cp16(uint32_t dst, const void* src){
    asm volatile("cp.async.cg.shared.global [%0], [%1], 16;" :: "r"(dst), "l"(src));
}
__device__ __forceinline__ void ldsm4(uint32_t &r0, uint32_t &r1, uint32_t &r2, uint32_t &r3, uint32_t addr){
    asm volatile("ldmatrix.sync.aligned.m8n8.x4.shared.b16 {%0,%1,%2,%3}, [%4];"
        : "=r"(r0), "=r"(r1), "=r"(r2), "=r"(r3) : "r"(addr));
}
__device__ __forceinline__ void ldsm4t(uint32_t &r0, uint32_t &r1, uint32_t &r2, uint32_t &r3, uint32_t addr){
    asm volatile("ldmatrix.sync.aligned.m8n8.x4.trans.shared.b16 {%0,%1,%2,%3}, [%4];"
        : "=r"(r0), "=r"(r1), "=r"(r2), "=r"(r3) : "r"(addr));
}
__device__ __forceinline__ void mma16816(float* c, uint32_t a0, uint32_t a1, uint32_t a2, uint32_t a3,
                                         uint32_t b0, uint32_t b1){
    asm volatile("mma.sync.aligned.m16n8k16.row.col.f32.bf16.bf16.f32 "
        "{%0,%1,%2,%3}, {%4,%5,%6,%7}, {%8,%9}, {%0,%1,%2,%3};"
        : "+f"(c[0]), "+f"(c[1]), "+f"(c[2]), "+f"(c[3])
        : "r"(a0), "r"(a1), "r"(a2), "r"(a3), "r"(b0), "r"(b1));
}

// =====================================================================
// split2: fp32 [rows x K] -> bf16 [rows x 2K] = [hi | lo]
// =====================================================================
__global__ __launch_bounds__(256) void split2(
    const float* __restrict__ in, int lda, int K,
    bf16* __restrict__ out, long rows)
{
    const int chunks = K >> 2;
    const long idx = (long)blockIdx.x * 256 + threadIdx.x;
    if (idx >= rows * chunks) return;
    const int row = (int)(idx / chunks);
    const int kc = (int)(idx - (long)row * chunks);
    const int blk = (kc * 8) / K;
    const int within = kc * 8 - blk * K;
    const float* src = in + (size_t)row * lda + within;
    F4U s0, s1; s0.f4 = *(const float4*)src; s1.f4 = *(const float4*)(src + 4);
    __nv_bfloat162 o[4];
    if (blk == 1){
        o[0] = lo2(s0.f[0], s0.f[1]); o[1] = lo2(s0.f[2], s0.f[3]);
        o[2] = lo2(s1.f[0], s1.f[1]); o[3] = lo2(s1.f[2], s1.f[3]);
    } else {
        o[0] = hi2(s0.f[0], s0.f[1]); o[1] = hi2(s0.f[2], s0.f[3]);
        o[2] = hi2(s1.f[0], s1.f[1]); o[3] = hi2(s1.f[2], s1.f[3]);
    }
    *(uint4*)&out[(size_t)row * (2 * K) + kc * 8] = *(uint4*)o;
}

struct WSpec { const float* src; bf16* dst; int K; long rows; long base; };
struct WTab  { WSpec e[10]; };

__global__ __launch_bounds__(256) void split2_wgt_all(WTab tab)
{
    const long idx = (long)blockIdx.x * 256 + threadIdx.x;
    int i = 0;
#pragma unroll
    for (int j = 1; j < 10; j++) if (idx >= tab.e[j].base) i = j;
    const WSpec w = tab.e[i];
    const long local = idx - w.base;
    const int chunks = w.K >> 2;
    if (local >= w.rows * chunks) return;
    const int row = (int)(local / chunks);
    const int kc = (int)(local - (long)row * chunks);
    const int blk = (kc * 8) / w.K;
    const int within = kc * 8 - blk * w.K;
    const float* src = w.src + (size_t)row * w.K + within;
    F4U s0, s1; s0.f4 = *(const float4*)src; s1.f4 = *(const float4*)(src + 4);
    __nv_bfloat162 o[4];
    if (blk == 1){
        o[0] = lo2(s0.f[0], s0.f[1]); o[1] = lo2(s0.f[2], s0.f[3]);
        o[2] = lo2(s1.f[0], s1.f[1]); o[3] = lo2(s1.f[2], s1.f[3]);
    } else {
        o[0] = hi2(s0.f[0], s0.f[1]); o[1] = hi2(s0.f[2], s0.f[3]);
        o[2] = hi2(s1.f[0], s1.f[1]); o[3] = hi2(s1.f[2], s1.f[3]);
    }
    *(uint4*)&w.dst[(size_t)row * (2 * w.K) + kc * 8] = *(uint4*)o;
}

// =====================================================================
// HMMA GEMM: 512 thr, 16 warps, CTA 128x128, BK templated.
// EPI: 0 none 1 bias 2 softplus 3 gelu 4 res 5 tri-bias
//      6 merged QKV+in: col<1536 -> C (tri-bias, pitch 1536);
//                       col>=1536 -> ((float*)C3) (no bias, pitch 2048)
// =====================================================================
template<int EPI, bool OUT3, int BK>
__global__ __launch_bounds__(512, 2) void hmma_gemm(
    const bf16* __restrict__ A2, const bf16* __restrict__ W2, int Ka,
    const float* __restrict__ bias, const float* __restrict__ bias_b,
    const float* __restrict__ bias_c, const float* __restrict__ res,
    float* __restrict__ C, bf16* __restrict__ C3, int N)
{
    const int PITCH = 2 * BK + 16;
    const int TB = 256 * PITCH;
    extern __shared__ char smem[];
    const uint32_t sb = smem_u32(smem);
    const int tid = threadIdx.x;
    const int wid = tid >> 5, lane = tid & 31;
    const int bm = blockIdx.y * 128;
    const int bn = blockIdx.x * 128;
    const int wm = wid & 3, wn = wid >> 2;
    const int gpitch = 2 * Ka;

    float acc[2][4][4];
#pragma unroll
    for (int i = 0; i < 2; i++)
#pragma unroll
        for (int j = 0; j < 4; j++)
#pragma unroll
            for (int e = 0; e < 4; e++) acc[i][j][e] = 0.f;

    const int NC = (3 * Ka) / BK;
    const int CPR = BK / 8;
    const int NCHUNK = 256 * CPR;
    const int ACH = 128 * CPR;

    auto load_tile = [&](int ci, uint32_t sbase){
        const int lcbase = ci * BK;
        int acol = lcbase; if (acol >= 2 * Ka) acol -= 2 * Ka;
        int wcol = lcbase; if (wcol >= Ka) wcol -= Ka;
#pragma unroll
        for (int cc = 0; cc < NCHUNK / 512; cc++){
            const int c = tid + cc * 512;
            if (c < ACH){
                const int row = c / CPR, ch = c % CPR;
                cp16(sbase + row * PITCH + ch * 16,
                     &A2[(size_t)(bm + row) * gpitch + acol + ch * 8]);
            } else {
                const int c2 = c - ACH;
                const int row = c2 / CPR, ch = c2 % CPR;
                int br = bn + row; if (br >= N) br = N - 1;
                cp16(sbase + 128 * PITCH + row * PITCH + ch * 16,
                     &W2[(size_t)br * gpitch + wcol + ch * 8]);
            }
        }
        asm volatile("cp.async.commit_group;" ::: "memory");
    };

    load_tile(0, sb);
    if (NC > 1) load_tile(1, sb + TB);

    const uint32_t aOff = (uint32_t)((wm * 32 + (lane & 15)) * PITCH + (lane >> 4) * 16);
    const uint32_t bOff = (uint32_t)(128 * PITCH +
                          (wn * 32 + (lane & 7) + ((lane & 16) ? 8 : 0)) * PITCH +
                          ((lane >> 3) & 1) * 16);

    for (int ci = 0; ci < NC; ci++){
        if (ci + 1 < NC) asm volatile("cp.async.wait_group 1;" ::: "memory");
        else             asm volatile("cp.async.wait_group 0;" ::: "memory");
        __syncthreads();
        if (ci + 2 < NC){
            const int nb = (ci + 2) % 3;
            load_tile(ci + 2, sb + (uint32_t)nb * TB);
        }
        const uint32_t cur = sb + (uint32_t)(ci % 3) * TB;

#pragma unroll
        for (int s = 0; s < BK / 16; s++){
            uint32_t a[2][4];
#pragma unroll
            for (int i = 0; i < 2; i++)
                ldsm4(a[i][0], a[i][1], a[i][2], a[i][3], cur + aOff + i * (16 * PITCH) + s * 32);
            uint32_t b0, b1, b2, b3, b4, b5, b6, b7;
            ldsm4(b0, b1, b2, b3, cur + bOff + s * 32);
            ldsm4(b4, b5, b6, b7, cur + bOff + 16 * PITCH + s * 32);
#pragma unroll
            for (int i = 0; i < 2; i++){
                mma16816(acc[i][0], a[i][0], a[i][1], a[i][2], a[i][3], b0, b1);
                mma16816(acc[i][1], a[i][0], a[i][1], a[i][2], a[i][3], b2, b3);
                mma16816(acc[i][2], a[i][0], a[i][1], a[i][2], a[i][3], b4, b5);
                mma16816(acc[i][3], a[i][0], a[i][1], a[i][2], a[i][3], b6, b7);
            }
        }
    }

    const int t4 = lane >> 2, tp = (lane & 3) * 2;
#pragma unroll
    for (int i = 0; i < 2; i++){
#pragma unroll
        for (int j = 0; j < 4; j++){
            const int col = bn + wn * 32 + j * 8 + tp;
            if (col >= N) continue;
            const int row0 = bm + wm * 32 + i * 16 + t4;
            float v0 = acc[i][j][0], v1 = acc[i][j][1];
            float v2 = acc[i][j][2], v3 = acc[i][j][3];
            if (EPI >= 1 && EPI <= 4){
                const float bb0 = bias[col], bb1 = bias[col + 1];
                v0 += bb0; v1 += bb1; v2 += bb0; v3 += bb1;
            }
            if (EPI == 5){
                const float* bp = (col < 512) ? bias : (col < 1024) ? (bias_b - 512) : (bias_c - 1024);
                const float bb0 = bp[col], bb1 = bp[col + 1];
                v0 += bb0; v1 += bb1; v2 += bb0; v3 += bb1;
            }
            if (EPI == 2){ v0 = softplus_f(v0); v1 = softplus_f(v1); v2 = softplus_f(v2); v3 = softplus_f(v3); }
            if (EPI == 3){ v0 = gelu_f(v0); v1 = gelu_f(v1); v2 = gelu_f(v2); v3 = gelu_f(v3); }
            if (EPI == 4){
                v0 += res[(size_t)row0 * N + col];
                v1 += res[(size_t)row0 * N + col + 1];
                v2 += res[(size_t)(row0 + 8) * N + col];
                v3 += res[(size_t)(row0 + 8) * N + col + 1];
            }
            if (EPI == 6){
                if (col < 1536){
                    const float* bp = (col < 512) ? bias : (col < 1024) ? (bias_b - 512) : (bias_c - 1024);
                    const float bb0 = bp[col], bb1 = bp[col + 1];
                    *(float2*)&C[(size_t)row0 * 1536 + col]       = make_float2(v0 + bb0, v1 + bb1);
                    *(float2*)&C[(size_t)(row0 + 8) * 1536 + col] = make_float2(v2 + bb0, v3 + bb1);
                } else {
                    float* xzout = (float*)C3;
                    const int cc = col - 1536;
                    *(float2*)&xzout[(size_t)row0 * 2048 + cc]       = make_float2(v0, v1);
                    *(float2*)&xzout[(size_t)(row0 + 8) * 2048 + cc] = make_float2(v2, v3);
                }
                continue;
            }
            if (OUT3){
                const size_t r0 = (size_t)row0 * (2 * N), r1 = (size_t)(row0 + 8) * (2 * N);
                *(__nv_bfloat162*)&C3[r0 + col]     = hi2(v0, v1);
                *(__nv_bfloat162*)&C3[r0 + N + col] = lo2(v0, v1);
                *(__nv_bfloat162*)&C3[r1 + col]     = hi2(v2, v3);
                *(__nv_bfloat162*)&C3[r1 + N + col] = lo2(v2, v3);
            } else {
                *(float2*)&C[(size_t)row0 * N + col]       = make_float2(v0, v1);
                *(float2*)&C[(size_t)(row0 + 8) * N + col] = make_float2(v2, v3);
            }
        }
    }
}
#define GEMM_SMEM32 (3 * 256 * 80)
#define GEMM_SMEM64 (3 * 256 * 144)

// =====================================================================
// Flash attention v2 (unchanged from R10/R11)
// =====================================================================
#define FQ 0
#define FK 34816
#define FV 52224
#define FMSK 70656
#define FLASH_SMEM 70912

__global__ __launch_bounds__(256, 2) void flash_mma(
    const float* __restrict__ QKV, const unsigned char* __restrict__ mask,
    bf16* __restrict__ AO2)
{
    extern __shared__ char sm[];
    const uint32_t sb = smem_u32(sm);
    float* mskf = (float*)(sm + FMSK);
    const int tid = threadIdx.x;
    const int w = tid >> 5, lane = tid & 31;
    const int t4 = lane >> 2, qq = lane & 3;
    const int bh = blockIdx.y, b = bh >> 3, h = bh & 7;
    const int q0 = blockIdx.x * 128;
    const size_t basebl = (size_t)b * cL;

    for (int idx = tid; idx < 2048; idx += 256){
        const int row = idx >> 4, c4 = idx & 15;
        F4U qv; qv.f4 = *(const float4*)&QKV[(basebl + q0 + row) * 1536 + h * 64 + c4 * 4];
        char* p = sm + FQ + row * 272 + c4 * 8;
        *(__nv_bfloat162*)(p)       = hi2(qv.f[0], qv.f[1]);
        *(__nv_bfloat162*)(p + 4)   = hi2(qv.f[2], qv.f[3]);
        *(__nv_bfloat162*)(p + 128) = lo2(qv.f[0], qv.f[1]);
        *(__nv_bfloat162*)(p + 132) = lo2(qv.f[2], qv.f[3]);
    }

    float m0 = -1e30f, m1 = -1e30f, l0 = 0.f, l1 = 0.f;
    float o[8][4];
#pragma unroll
    for (int nt = 0; nt < 8; nt++)
#pragma unroll
        for (int e = 0; e < 4; e++) o[nt][e] = 0.f;

    for (int jt = 0; jt < cL / 64; jt++){
        __syncthreads();
        for (int idx = tid; idx < 1024; idx += 256){
            const int row = idx >> 4, c4 = idx & 15;
            const size_t gr = (basebl + jt * 64 + row) * 1536 + h * 64 + c4 * 4;
            F4U kv; kv.f4 = *(const float4*)&QKV[gr + 512];
            F4U vv; vv.f4 = *(const float4*)&QKV[gr + 1024];
            char* pk = sm + FK + row * 272 + c4 * 8;
            *(__nv_bfloat162*)(pk)       = hi2(kv.f[0], kv.f[1]);
            *(__nv_bfloat162*)(pk + 4)   = hi2(kv.f[2], kv.f[3]);
            *(__nv_bfloat162*)(pk + 128) = lo2(kv.f[0], kv.f[1]);
            *(__nv_bfloat162*)(pk + 132) = lo2(kv.f[2], kv.f[3]);
            char* ph = sm + FV + row * 144 + c4 * 8;
            *(__nv_bfloat162*)(ph)     = hi2(vv.f[0], vv.f[1]);
            *(__nv_bfloat162*)(ph + 4) = hi2(vv.f[2], vv.f[3]);
            char* pl = sm + FV + (64 + row) * 144 + c4 * 8;
            *(__nv_bfloat162*)(pl)     = lo2(vv.f[0], vv.f[1]);
            *(__nv_bfloat162*)(pl + 4) = lo2(vv.f[2], vv.f[3]);
        }
        if (tid < 64) mskf[tid] = mask[b * cL + jt * 64 + tid] ? -1e30f : 0.0f;
        __syncthreads();

        float sacc[8][4];
#pragma unroll
        for (int nt = 0; nt < 8; nt++)
#pragma unroll
            for (int e = 0; e < 4; e++) sacc[nt][e] = 0.f;

#pragma unroll
        for (int s = 0; s < 12; s++){
            const int ab = (s < 4) ? s * 32 : (s < 8) ? 128 + (s - 4) * 32 : (s - 8) * 32;
            const int bb = (s < 8) ? (s & 3) * 32 : 128 + (s - 8) * 32;
            uint32_t a0, a1, a2, a3;
            ldsm4(a0, a1, a2, a3, sb + FQ + (w * 16 + (lane & 15)) * 272 + ab + (lane >> 4) * 16);
#pragma unroll
            for (int kc = 0; kc < 4; kc++){
                uint32_t b0, b1, b2, b3;
                ldsm4(b0, b1, b2, b3,
                      sb + FK + (kc * 16 + (lane & 7) + ((lane & 16) ? 8 : 0)) * 272 + bb + ((lane >> 3) & 1) * 16);
                mma16816(sacc[2 * kc],     a0, a1, a2, a3, b0, b1);
                mma16816(sacc[2 * kc + 1], a0, a1, a2, a3, b2, b3);
            }
        }

        float mx0 = -1e30f, mx1 = -1e30f;
#pragma unroll
        for (int nt = 0; nt < 8; nt++){
            const float2 mk = *(const float2*)&mskf[nt * 8 + qq * 2];
            sacc[nt][0] = sacc[nt][0] * 0.125f + mk.x;
            sacc[nt][1] = sacc[nt][1] * 0.125f + mk.y;
            sacc[nt][2] = sacc[nt][2] * 0.125f + mk.x;
            sacc[nt][3] = sacc[nt][3] * 0.125f + mk.y;
            mx0 = fmaxf(mx0, fmaxf(sacc[nt][0], sacc[nt][1]));
            mx1 = fmaxf(mx1, fmaxf(sacc[nt][2], sacc[nt][3]));
        }
        mx0 = fmaxf(mx0, __shfl_xor_sync(0xffffffffu, mx0, 1));
        mx0 = fmaxf(mx0, __shfl_xor_sync(0xffffffffu, mx0, 2));
        mx1 = fmaxf(mx1, __shfl_xor_sync(0xffffffffu, mx1, 1));
        mx1 = fmaxf(mx1, __shfl_xor_sync(0xffffffffu, mx1, 2));
        const float mn0 = fmaxf(m0, mx0), mn1 = fmaxf(m1, mx1);
        const float fac0 = __expf(m0 - mn0), fac1 = __expf(m1 - mn1);
        m0 = mn0; m1 = mn1;
        float sum0 = 0.f, sum1 = 0.f;
#pragma unroll
        for (int nt = 0; nt < 8; nt++){
            sacc[nt][0] = __expf(sacc[nt][0] - mn0);
            sacc[nt][1] = __expf(sacc[nt][1] - mn0);
            sacc[nt][2] = __expf(sacc[nt][2] - mn1);
            sacc[nt][3] = __expf(sacc[nt][3] - mn1);
            sum0 += sacc[nt][0] + sacc[nt][1];
            sum1 += sacc[nt][2] + sacc[nt][3];
        }
        sum0 += __shfl_xor_sync(0xffffffffu, sum0, 1);
        sum0 += __shfl_xor_sync(0xffffffffu, sum0, 2);
        sum1 += __shfl_xor_sync(0xffffffffu, sum1, 1);
        sum1 += __shfl_xor_sync(0xffffffffu, sum1, 2);
        l0 = l0 * fac0 + sum0;
        l1 = l1 * fac1 + sum1;
#pragma unroll
        for (int nt = 0; nt < 8; nt++){
            o[nt][0] *= fac0; o[nt][1] *= fac0;
            o[nt][2] *= fac1; o[nt][3] *= fac1;
        }

        uint32_t Ph[4][4], Pl[4][4];
#pragma unroll
        for (int kk = 0; kk < 4; kk++){
            Ph[kk][0] = hi2u(sacc[2*kk][0],   sacc[2*kk][1]);
            Ph[kk][1] = hi2u(sacc[2*kk][2],   sacc[2*kk][3]);
            Ph[kk][2] = hi2u(sacc[2*kk+1][0], sacc[2*kk+1][1]);
            Ph[kk][3] = hi2u(sacc[2*kk+1][2], sacc[2*kk+1][3]);
            Pl[kk][0] = lo2u(sacc[2*kk][0],   sacc[2*kk][1]);
            Pl[kk][1] = lo2u(sacc[2*kk][2],   sacc[2*kk][3]);
            Pl[kk][2] = lo2u(sacc[2*kk+1][0], sacc[2*kk+1][1]);
            Pl[kk][3] = lo2u(sacc[2*kk+1][2], sacc[2*kk+1][3]);
        }

#pragma unroll
        for (int s = 0; s < 12; s++){
            const uint32_t* af = (s < 4) ? Ph[s] : (s < 8) ? Pl[s - 4] : Ph[s - 8];
            const int vr = (s < 8) ? (s & 3) * 16 : 64 + (s - 8) * 16;
#pragma unroll
            for (int nb = 0; nb < 4; nb++){
                uint32_t v0, v1, v2, v3;
                ldsm4t(v0, v1, v2, v3,
                       sb + FV + (vr + (lane & 15)) * 144 + (nb * 16 + ((lane & 16) ? 8 : 0)) * 2);
                mma16816(o[2 * nb],     af[0], af[1], af[2], af[3], v0, v1);
                mma16816(o[2 * nb + 1], af[0], af[1], af[2], af[3], v2, v3);
            }
        }
    }

    const float i0 = 1.0f / l0, i1 = 1.0f / l1;
    const size_t gA = (basebl + q0 + w * 16 + t4) * 1024;
    const size_t gB = gA + 8 * 1024;
#pragma unroll
    for (int nt = 0; nt < 8; nt++){
        const float a0 = o[nt][0] * i0, a1 = o[nt][1] * i0;
        const float a2 = o[nt][2] * i1, a3 = o[nt][3] * i1;
        const int col = h * 64 + nt * 8 + qq * 2;
        *(__nv_bfloat162*)&AO2[gA + col]       = hi2(a0, a1);
        *(__nv_bfloat162*)&AO2[gA + 512 + col] = lo2(a0, a1);
        *(__nv_bfloat162*)&AO2[gB + col]       = hi2(a2, a3);
        *(__nv_bfloat162*)&AO2[gB + 512 + col] = lo2(a2, a3);
    }
}

// =====================================================================
// conv_silu v2: thread owns 4 timesteps x 4 channels (sliding window:
// 7 row-loads for 16 outputs instead of 16).
// =====================================================================
__global__ __launch_bounds__(256) void conv_silu(
    const float* __restrict__ xz, const float* __restrict__ cw,
    const float* __restrict__ cb, float* __restrict__ u, bf16* __restrict__ u2)
{
    const long idx = (long)blockIdx.x * 256 + threadIdx.x;   // over (M/4)*256
    const int c = (int)(idx & 255) * 4;
    const int mg = (int)(idx >> 8);                           // m-group of 4
    const int b = mg / (cL / 4), lg = mg % (cL / 4);
    const int l0 = lg * 4;
    const size_t rowb = (size_t)(b * cL + l0) * (2 * cDI) + c;

    F4U w0, w1, w2, w3, bias;
    w0.f4 = *(const float4*)&cw[c * 4];
    w1.f4 = *(const float4*)&cw[(c + 1) * 4];
    w2.f4 = *(const float4*)&cw[(c + 2) * 4];
    w3.f4 = *(const float4*)&cw[(c + 3) * 4];
    bias.f4 = *(const float4*)&cb[c];

    F4U xv[7];
#pragma unroll
    for (int i = 0; i < 7; i++){
        const int l = l0 + i - 3;
        if (l >= 0) xv[i].f4 = *(const float4*)&xz[rowb + (size_t)(i - 3) * (2 * cDI)];
        else        xv[i].f4 = make_float4(0.f, 0.f, 0.f, 0.f);
    }

#pragma unroll
    for (int j = 0; j < 4; j++){
        F4U acc; acc.f4 = bias.f4;
#pragma unroll
        for (int k = 0; k < 4; k++){
            acc.f[0] += xv[j + k].f[0] * w0.f[k];
            acc.f[1] += xv[j + k].f[1] * w1.f[k];
            acc.f[2] += xv[j + k].f[2] * w2.f[k];
            acc.f[3] += xv[j + k].f[3] * w3.f[k];
        }
#pragma unroll
        for (int e = 0; e < 4; e++) acc.f[e] = acc.f[e] / (1.0f + __expf(-acc.f[e]));
        const int m = b * cL + l0 + j;
        *(float4*)&u[(size_t)m * cDI + c] = acc.f4;
        const size_t r2 = (size_t)m * 2048;
        __nv_bfloat162 hh[2] = { hi2(acc.f[0], acc.f[1]), hi2(acc.f[2], acc.f[3]) };
        __nv_bfloat162 ll[2] = { lo2(acc.f[0], acc.f[1]), lo2(acc.f[2], acc.f[3]) };
        *(uint2*)&u2[r2 + c]        = *(uint2*)hh;
        *(uint2*)&u2[r2 + 1024 + c] = *(uint2*)ll;
    }
}

// =====================================================================
// Selective scan (R11 version — known good): 2 d per warp, direct loads
// =====================================================================
__global__ __launch_bounds__(256) void mamba_scan(
    const float* __restrict__ delta, const float* __restrict__ u,
    const float* __restrict__ xdbc, const float* __restrict__ xz,
    const float* __restrict__ A_log, const float* __restrict__ Dssm,
    bf16* __restrict__ y2)
{
    const int warp = threadIdx.x >> 5, lane = threadIdx.x & 31;
    const int half = lane >> 4, sl = lane & 15;
    const int d = blockIdx.x * 16 + warp * 2 + half;
    const int b = blockIdx.y;
    float a[4], hh[4];
#pragma unroll
    for (int k = 0; k < 4; k++){
        a[k] = -__expf(A_log[d * cS + sl * 4 + k]);
        hh[k] = 0.f;
    }
    const float Dd = Dssm[d];
    const size_t base = (size_t)b * cL;

    for (int t = 0; t < cL; t++){
        const size_t m = base + t;
        const float dt = __ldg(&delta[m * cDI + d]);
        const float uu = __ldg(&u[m * cDI + d]);
        F4U Bv, Cv;
        Bv.f4 = *(const float4*)&xdbc[m * 160 + 32 + sl * 4];
        Cv.f4 = *(const float4*)&xdbc[m * 160 + 96 + sl * 4];
        const float du = dt * uu;
        float p = 0.f;
#pragma unroll
        for (int k = 0; k < 4; k++){
            hh[k] = hh[k] * __expf(dt * a[k]) + du * Bv.f[k];
            p += hh[k] * Cv.f[k];
        }
        p += __shfl_xor_sync(0xffffffffu, p, 8);
        p += __shfl_xor_sync(0xffffffffu, p, 4);
        p += __shfl_xor_sync(0xffffffffu, p, 2);
        p += __shfl_xor_sync(0xffffffffu, p, 1);
        if (sl == 0){
            const float z = xz[m * (2 * cDI) + cDI + d];
            float yv = p + uu * Dd;
            yv *= z / (1.0f + __expf(-z));
            const size_t r2 = m * 2048;
            y2[r2 + d]        = hi_bf(yv);
            y2[r2 + 1024 + d] = lo_bf(yv);
        }
    }
}

// =====================================================================
// Fused residual + LN1 + LN2
// =====================================================================
__device__ __forceinline__ float blockSum256(float v, float* red){
#pragma unroll
    for (int off = 16; off > 0; off >>= 1) v += __shfl_xor_sync(0xffffffffu, v, off);
    if ((threadIdx.x & 31) == 0) red[threadIdx.x >> 5] = v;
    __syncthreads();
    const float s = red[0]+red[1]+red[2]+red[3]+red[4]+red[5]+red[6]+red[7];
    __syncthreads();
    return s;
}

__global__ __launch_bounds__(256) void ln_fuse(
    const float* __restrict__ xf, const float* __restrict__ attn, const float* __restrict__ mamba,
    const float* __restrict__ g1, const float* __restrict__ b1,
    const float* __restrict__ g2, const float* __restrict__ b2,
    float* __restrict__ h, bf16* __restrict__ hn2)
{
    __shared__ float red[8];
    const size_t m = blockIdx.x;
    const int t = threadIdx.x * 2;
    const size_t r = m * cD;
    const float2 xv = *(const float2*)&xf[r + t];
    const float2 av = *(const float2*)&attn[r + t];
    const float2 mv = *(const float2*)&mamba[r + t];
    float v0 = xv.x + av.x + mv.x;
    float v1 = xv.y + av.y + mv.y;

    const float mean = blockSum256(v0 + v1, red) * (1.0f / cD);
    const float d0 = v0 - mean, d1 = v1 - mean;
    const float var = blockSum256(d0 * d0 + d1 * d1, red) * (1.0f / cD);
    const float inv = rsqrtf(var + 1e-5f);
    const float2 g1v = *(const float2*)&g1[t];
    const float2 b1v = *(const float2*)&b1[t];
    const float h0 = d0 * inv * g1v.x + b1v.x;
    const float h1 = d1 * inv * g1v.y + b1v.y;
    *(float2*)&h[r + t] = make_float2(h0, h1);

    const float mean2 = blockSum256(h0 + h1, red) * (1.0f / cD);
    const float e0 = h0 - mean2, e1 = h1 - mean2;
    const float var2 = blockSum256(e0 * e0 + e1 * e1, red) * (1.0f / cD);
    const float inv2 = rsqrtf(var2 + 1e-6f);
    const float2 g2v = *(const float2*)&g2[t];
    const float2 b2v = *(const float2*)&b2[t];
    const float n0 = e0 * inv2 * g2v.x + b2v.x;
    const float n1 = e1 * inv2 * g2v.y + b2v.y;
    const size_t r2 = m * 1024;
    *(__nv_bfloat162*)&hn2[r2 + t]       = hi2(n0, n1);
    *(__nv_bfloat162*)&hn2[r2 + 512 + t] = lo2(n0, n1);
}

// =====================================================================
// Launch
// =====================================================================
static inline int sgrid2(long rows, int K){
    return (int)((rows * (K >> 2) + 255) / 256);
}

extern "C" void kernel_launch(void* const* d_in, const int* in_sizes, int n_in,
                              void* d_out, int out_size)
{
    (void)in_sizes; (void)n_in; (void)out_size;
    const float* x      = (const float*)d_in[0];
    const unsigned char* mask = (const unsigned char*)d_in[1];
    const float* Wq = (const float*)d_in[2];  const float* bq = (const float*)d_in[3];
    const float* Wk = (const float*)d_in[4];  const float* bk = (const float*)d_in[5];
    const float* Wv = (const float*)d_in[6];  const float* bv = (const float*)d_in[7];
    const float* Wo = (const float*)d_in[8];  const float* bo = (const float*)d_in[9];
    const float* in_w   = (const float*)d_in[10];
    const float* conv_w = (const float*)d_in[11];
    const float* conv_b = (const float*)d_in[12];
    const float* xproj_w= (const float*)d_in[13];
    const float* dt_w   = (const float*)d_in[14];
    const float* dt_b   = (const float*)d_in[15];
    const float* A_log  = (const float*)d_in[16];
    const float* Dssm   = (const float*)d_in[17];
    const float* outp_w = (const float*)d_in[18];
    const float* ln1g   = (const float*)d_in[19];
    const float* ln1b   = (const float*)d_in[20];
    const float* fw1    = (const float*)d_in[21];
    const float* fb1    = (const float*)d_in[22];
    const float* fw2    = (const float*)d_in[23];
    const float* fb2    = (const float*)d_in[24];
    const float* ln2g   = (const float*)d_in[25];
    const float* ln2b   = (const float*)d_in[26];
    float* out = (float*)d_out;

    float *qkv,*attn,*xz,*u,*xdbc,*dlt,*mmb,*h;
    cudaGetSymbolAddress((void**)&qkv,  g_qkv);
    cudaGetSymbolAddress((void**)&attn, g_attn);
    cudaGetSymbolAddress((void**)&xz,   g_xz);
    cudaGetSymbolAddress((void**)&u,    g_u);
    cudaGetSymbolAddress((void**)&xdbc, g_xdbc);
    cudaGetSymbolAddress((void**)&dlt,  g_dlt);
    cudaGetSymbolAddress((void**)&mmb,  g_mmb);
    cudaGetSymbolAddress((void**)&h,    g_h);

    bf16 *px2,*pao2,*pu2,*pxdbc2,*py2,*phn2,*pff12;
    bf16 *pwqi,*pwo,*pwxp,*pwdt,*pwout,*pwf1,*pwf2;
    cudaGetSymbolAddress((void**)&px2,   gx2);
    cudaGetSymbolAddress((void**)&pao2,  gao2);
    cudaGetSymbolAddress((void**)&pu2,   gu2);
    cudaGetSymbolAddress((void**)&pxdbc2,gxdbc2);
    cudaGetSymbolAddress((void**)&py2,   gy2);
    cudaGetSymbolAddress((void**)&phn2,  ghn2);
    cudaGetSymbolAddress((void**)&pff12, gff12);
    cudaGetSymbolAddress((void**)&pwqi,  wqi2);
    cudaGetSymbolAddress((void**)&pwo,   wo2);
    cudaGetSymbolAddress((void**)&pwxp,  wxp2);
    cudaGetSymbolAddress((void**)&pwdt,  wdt2);
    cudaGetSymbolAddress((void**)&pwout, wout2);
    cudaGetSymbolAddress((void**)&pwf1,  wff12);
    cudaGetSymbolAddress((void**)&pwf2,  wff22);

    cudaFuncSetAttribute(flash_mma, cudaFuncAttributeMaxDynamicSharedMemorySize, FLASH_SMEM);
    cudaFuncSetAttribute(hmma_gemm<0,false,64>, cudaFuncAttributeMaxDynamicSharedMemorySize, GEMM_SMEM64);
    cudaFuncSetAttribute(hmma_gemm<1,false,64>, cudaFuncAttributeMaxDynamicSharedMemorySize, GEMM_SMEM64);
    cudaFuncSetAttribute(hmma_gemm<3,true,64>,  cudaFuncAttributeMaxDynamicSharedMemorySize, GEMM_SMEM64);
    cudaFuncSetAttribute(hmma_gemm<4,false,64>, cudaFuncAttributeMaxDynamicSharedMemorySize, GEMM_SMEM64);
    cudaFuncSetAttribute(hmma_gemm<6,false,64>, cudaFuncAttributeMaxDynamicSharedMemorySize, GEMM_SMEM64);
    cudaFuncSetAttribute(hmma_gemm<2,false,32>, cudaFuncAttributeMaxDynamicSharedMemorySize, GEMM_SMEM32);

    // ---- fused weight-split table (QKV + in_proj concatenated) ----
    WTab tab;
    long base = 0;
    auto add = [&](int i, const float* src, bf16* dst, int K, long rows){
        tab.e[i] = {src, dst, K, rows, base};
        base += rows * (K >> 2);
    };
    add(0, Wq,      pwqi,                512,  512);
    add(1, Wk,      pwqi + 512 * 1024,   512,  512);
    add(2, Wv,      pwqi + 1024 * 1024,  512,  512);
    add(3, in_w,    pwqi + 1536 * 1024,  512,  2048);
    add(4, Wo,      pwo,                 512,  512);
    add(5, xproj_w, pwxp,                1024, 160);
    add(6, dt_w,    pwdt,                32,   1024);
    add(7, outp_w,  pwout,               1024, 512);
    add(8, fw1,     pwf1,                512,  2048);
    add(9, fw2,     pwf2,                2048, 512);
    const int wgrid = (int)((base + 255) / 256);

    cudaStream_t s0 = 0, sB = g_sh.sB;

    split2_wgt_all<<<wgrid, 256, 0, s0>>>(tab);
    split2<<<sgrid2(cM, 512), 256, 0, s0>>>(x, 512, 512, px2, cM);

    // merged QKV + in_proj GEMM (N=3584)
    hmma_gemm<6,false,64><<<dim3(28, 72), 512, GEMM_SMEM64, s0>>>(px2, pwqi, 512, bq, bk, bv, nullptr, qkv, (bf16*)xz, 3584);

    cudaEventRecord(g_sh.evRoot, s0);
    cudaStreamWaitEvent(sB, g_sh.evRoot, 0);

    // mamba branch on sB
    conv_silu<<<(cM / 4), 256, 0, sB>>>(xz, conv_w, conv_b, u, pu2);
    hmma_gemm<0,false,64><<<dim3(2, 72), 512, GEMM_SMEM64, sB>>>(pu2, pwxp, 1024, nullptr, nullptr, nullptr, nullptr, xdbc, nullptr, 160);
    split2<<<sgrid2(cM, 32), 256, 0, sB>>>(xdbc, 160, 32, pxdbc2, cM);
    hmma_gemm<2,false,32><<<dim3(8, 72), 512, GEMM_SMEM32, sB>>>(pxdbc2, pwdt, 32, dt_b, nullptr, nullptr, nullptr, dlt, nullptr, 1024);
    mamba_scan<<<dim3(cDI / 16, cB), 256, 0, sB>>>(dlt, u, xdbc, xz, A_log, Dssm, py2);
    hmma_gemm<0,false,64><<<dim3(4, 72), 512, GEMM_SMEM64, sB>>>(py2, pwout, 1024, nullptr, nullptr, nullptr, nullptr, mmb, nullptr, 512);
    cudaEventRecord(g_sh.evB, sB);

    // attention branch on s0
    flash_mma<<<dim3(cL / 128, cB * 8), 256, FLASH_SMEM, s0>>>(qkv, mask, pao2);
    hmma_gemm<1,false,64><<<dim3(4, 72), 512, GEMM_SMEM64, s0>>>(pao2, pwo, 512, bo, nullptr, nullptr, nullptr, attn, nullptr, 512);

    cudaStreamWaitEvent(s0, g_sh.evB, 0);
    ln_fuse<<<cM, 256, 0, s0>>>(x, attn, mmb, ln1g, ln1b, ln2g, ln2b, h, phn2);
    hmma_gemm<3,true,64><<<dim3(16, 72), 512, GEMM_SMEM64, s0>>>(phn2, pwf1, 512, fb1, nullptr, nullptr, nullptr, nullptr, pff12, 2048);
    hmma_gemm<4,false,64><<<dim3(4, 72), 512, GEMM_SMEM64, s0>>>(pff12, pwf2, 2048, fb2, nullptr, nullptr, h, out, nullptr, 512);
}

// round 16
// speedup vs baseline: 1.7658x; 1.5130x over previous
#include <cuda_runtime.h>
#include <cuda_bf16.h>
#include <cstdint>
#include <math.h>

typedef __nv_bfloat16 bf16;

// ---------------- dims ----------------
static const int cB  = 8;
static const int cL  = 1152;      // T*W
static const int cD  = 512;
static const int cDI = 1024;
static const int cS  = 64;
static const int cDFF= 2048;
static const int cM  = 9216;      // B*L

// ---------------- fp32 workspaces ----------------
__device__ float g_attn[cM*cD];
__device__ float g_xz  [cM*2*cDI];
__device__ float g_u   [cM*cDI];
__device__ float g_xdbc[cM*160];
__device__ float g_dlt [cM*cDI];
__device__ float g_mmb [cM*cD];
__device__ float g_h   [cM*cD];

// ---------------- bf16 split-2 storage [hi|lo] ----------------
__device__ bf16 g_qkv2[cM*3072];   // QKV: cols 0-1535 hi, 1536-3071 lo
__device__ bf16 gx2   [cM*1024];
__device__ bf16 gao2  [cM*1024];
__device__ bf16 gu2   [cM*2048];
__device__ bf16 gxdbc2[cM*64];
__device__ bf16 gy2   [cM*2048];
__device__ bf16 ghn2  [cM*1024];
__device__ bf16 gff12 [cM*4096];

__device__ bf16 wqi2 [3584*1024];   // QKV rows 0-1535, in_proj rows 1536-3583
__device__ bf16 wo2  [512*1024];
__device__ bf16 wxp2 [160*2048];
__device__ bf16 wdt2 [1024*64];
__device__ bf16 wout2[512*2048];
__device__ bf16 wff12[2048*1024];
__device__ bf16 wff22[512*4096];

// ---------------- streams ----------------
struct StreamHolder {
    cudaStream_t sB;
    cudaEvent_t evRoot, evB;
    StreamHolder(){
        cudaStreamCreateWithFlags(&sB, cudaStreamNonBlocking);
        cudaEventCreateWithFlags(&evRoot, cudaEventDisableTiming);
        cudaEventCreateWithFlags(&evB,   cudaEventDisableTiming);
    }
};
static StreamHolder g_sh;

// ---------------- helpers ----------------
union F4U { float4 f4; unsigned long long l[2]; float f[4]; };
union BU  { __nv_bfloat162 b; uint32_t u; };

__device__ __forceinline__ float softplus_f(float v){
    return fmaxf(v, 0.0f) + log1pf(__expf(-fabsf(v)));
}
__device__ __forceinline__ float gelu_f(float v){
    return 0.5f * v * (1.0f + erff(v * 0.70710678118654752f));
}
__device__ __forceinline__ bf16 hi_bf(float a){ return __float2bfloat16(a); }
__device__ __forceinline__ bf16 lo_bf(float a){
    bf16 h = __float2bfloat16(a);
    return __float2bfloat16(a - __bfloat162float(h));
}
__device__ __forceinline__ __nv_bfloat162 hi2(float a, float b){
    return __floats2bfloat162_rn(a, b);
}
__device__ __forceinline__ __nv_bfloat162 lo2(float a, float b){
    __nv_bfloat162 h = __floats2bfloat162_rn(a, b);
    return __floats2bfloat162_rn(a - __bfloat162float(h.x), b - __bfloat162float(h.y));
}
__device__ __forceinline__ uint32_t hi2u(float a, float b){ BU t; t.b = hi2(a, b); return t.u; }
__device__ __forceinline__ uint32_t lo2u(float a, float b){ BU t; t.b = lo2(a, b); return t.u; }

__device__ __forceinline__ uint32_t smem_u32(const void* p){
    uint32_t a;
    asm("{ .reg .u64 t; cvta.to.shared.u64 t, %1; cvt.u32.u64 %0, t; }" : "=r"(a) : "l"(p));
    return a;
}
__device__ __forceinline__ void cp16(uint32_t dst, const void* src){
    asm volatile("cp.async.cg.shared.global [%0], [%1], 16;" :: "r"(dst), "l"(src));
}
__device__ __forceinline__ void ldsm4(uint32_t &r0, uint32_t &r1, uint32_t &r2, uint32_t &r3, uint32_t addr){
    asm volatile("ldmatrix.sync.aligned.m8n8.x4.shared.b16 {%0,%1,%2,%3}, [%4];"
        : "=r"(r0), "=r"(r1), "=r"(r2), "=r"(r3) : "r"(addr));
}
__device__ __forceinline__ void ldsm4t(uint32_t &r0, uint32_t &r1, uint32_t &r2, uint32_t &r3, uint32_t addr){
    asm volatile("ldmatrix.sync.aligned.m8n8.x4.trans.shared.b16 {%0,%1,%2,%3}, [%4];"
        : "=r"(r0), "=r"(r1), "=r"(r2), "=r"(r3) : "r"(addr));
}
__device__ __forceinline__ void mma16816(float* c, uint32_t a0, uint32_t a1, uint32_t a2, uint32_t a3,
                                         uint32_t b0, uint32_t b1){
    asm volatile("mma.sync.aligned.m16n8k16.row.col.f32.bf16.bf16.f32 "
        "{%0,%1,%2,%3}, {%4,%5,%6,%7}, {%8,%9}, {%0,%1,%2,%3};"
        : "+f"(c[0]), "+f"(c[1]), "+f"(c[2]), "+f"(c[3])
        : "r"(a0), "r"(a1), "r"(a2), "r"(a3), "r"(b0), "r"(b1));
}

// =====================================================================
// split2: fp32 [rows x K] -> bf16 [rows x 2K] = [hi | lo]
// =====================================================================
__global__ __launch_bounds__(256) void split2(
    const float* __restrict__ in, int lda, int K,
    bf16* __restrict__ out, long rows)
{
    const int chunks = K >> 2;
    const long idx = (long)blockIdx.x * 256 + threadIdx.x;
    if (idx >= rows * chunks) return;
    const int row = (int)(idx / chunks);
    const int kc = (int)(idx - (long)row * chunks);
    const int blk = (kc * 8) / K;
    const int within = kc * 8 - blk * K;
    const float* src = in + (size_t)row * lda + within;
    F4U s0, s1; s0.f4 = *(const float4*)src; s1.f4 = *(const float4*)(src + 4);
    __nv_bfloat162 o[4];
    if (blk == 1){
        o[0] = lo2(s0.f[0], s0.f[1]); o[1] = lo2(s0.f[2], s0.f[3]);
        o[2] = lo2(s1.f[0], s1.f[1]); o[3] = lo2(s1.f[2], s1.f[3]);
    } else {
        o[0] = hi2(s0.f[0], s0.f[1]); o[1] = hi2(s0.f[2], s0.f[3]);
        o[2] = hi2(s1.f[0], s1.f[1]); o[3] = hi2(s1.f[2], s1.f[3]);
    }
    *(uint4*)&out[(size_t)row * (2 * K) + kc * 8] = *(uint4*)o;
}

struct WSpec { const float* src; bf16* dst; int K; long rows; long base; };
struct WTab  { WSpec e[10]; };

__global__ __launch_bounds__(256) void split2_wgt_all(WTab tab)
{
    const long idx = (long)blockIdx.x * 256 + threadIdx.x;
    int i = 0;
#pragma unroll
    for (int j = 1; j < 10; j++) if (idx >= tab.e[j].base) i = j;
    const WSpec w = tab.e[i];
    const long local = idx - w.base;
    const int chunks = w.K >> 2;
    if (local >= w.rows * chunks) return;
    const int row = (int)(local / chunks);
    const int kc = (int)(local - (long)row * chunks);
    const int blk = (kc * 8) / w.K;
    const int within = kc * 8 - blk * w.K;
    const float* src = w.src + (size_t)row * w.K + within;
    F4U s0, s1; s0.f4 = *(const float4*)src; s1.f4 = *(const float4*)(src + 4);
    __nv_bfloat162 o[4];
    if (blk == 1){
        o[0] = lo2(s0.f[0], s0.f[1]); o[1] = lo2(s0.f[2], s0.f[3]);
        o[2] = lo2(s1.f[0], s1.f[1]); o[3] = lo2(s1.f[2], s1.f[3]);
    } else {
        o[0] = hi2(s0.f[0], s0.f[1]); o[1] = hi2(s0.f[2], s0.f[3]);
        o[2] = hi2(s1.f[0], s1.f[1]); o[3] = hi2(s1.f[2], s1.f[3]);
    }
    *(uint4*)&w.dst[(size_t)row * (2 * w.K) + kc * 8] = *(uint4*)o;
}

// =====================================================================
// HMMA GEMM: 512 thr, 16 warps, CTA 128x128, BK templated.
// EPI: 0 none 1 bias 2 softplus 3 gelu 4 res 5 tri-bias
//      6 merged: col<1536 -> bf16 [hi|lo] into C3 (pitch 3072, tri-bias);
//                col>=1536 -> fp32 into C (xz, pitch 2048, no bias)
// =====================================================================
template<int EPI, bool OUT3, int BK>
__global__ __launch_bounds__(512, 2) void hmma_gemm(
    const bf16* __restrict__ A2, const bf16* __restrict__ W2, int Ka,
    const float* __restrict__ bias, const float* __restrict__ bias_b,
    const float* __restrict__ bias_c, const float* __restrict__ res,
    float* __restrict__ C, bf16* __restrict__ C3, int N)
{
    const int PITCH = 2 * BK + 16;
    const int TB = 256 * PITCH;
    extern __shared__ char smem[];
    const uint32_t sb = smem_u32(smem);
    const int tid = threadIdx.x;
    const int wid = tid >> 5, lane = tid & 31;
    const int bm = blockIdx.y * 128;
    const int bn = blockIdx.x * 128;
    const int wm = wid & 3, wn = wid >> 2;
    const int gpitch = 2 * Ka;

    float acc[2][4][4];
#pragma unroll
    for (int i = 0; i < 2; i++)
#pragma unroll
        for (int j = 0; j < 4; j++)
#pragma unroll
            for (int e = 0; e < 4; e++) acc[i][j][e] = 0.f;

    const int NC = (3 * Ka) / BK;
    const int CPR = BK / 8;
    const int NCHUNK = 256 * CPR;
    const int ACH = 128 * CPR;

    auto load_tile = [&](int ci, uint32_t sbase){
        const int lcbase = ci * BK;
        int acol = lcbase; if (acol >= 2 * Ka) acol -= 2 * Ka;
        int wcol = lcbase; if (wcol >= Ka) wcol -= Ka;
#pragma unroll
        for (int cc = 0; cc < NCHUNK / 512; cc++){
            const int c = tid + cc * 512;
            if (c < ACH){
                const int row = c / CPR, ch = c % CPR;
                cp16(sbase + row * PITCH + ch * 16,
                     &A2[(size_t)(bm + row) * gpitch + acol + ch * 8]);
            } else {
                const int c2 = c - ACH;
                const int row = c2 / CPR, ch = c2 % CPR;
                int br = bn + row; if (br >= N) br = N - 1;
                cp16(sbase + 128 * PITCH + row * PITCH + ch * 16,
                     &W2[(size_t)br * gpitch + wcol + ch * 8]);
            }
        }
        asm volatile("cp.async.commit_group;" ::: "memory");
    };

    load_tile(0, sb);
    if (NC > 1) load_tile(1, sb + TB);

    const uint32_t aOff = (uint32_t)((wm * 32 + (lane & 15)) * PITCH + (lane >> 4) * 16);
    const uint32_t bOff = (uint32_t)(128 * PITCH +
                          (wn * 32 + (lane & 7) + ((lane & 16) ? 8 : 0)) * PITCH +
                          ((lane >> 3) & 1) * 16);

    for (int ci = 0; ci < NC; ci++){
        if (ci + 1 < NC) asm volatile("cp.async.wait_group 1;" ::: "memory");
        else             asm volatile("cp.async.wait_group 0;" ::: "memory");
        __syncthreads();
        if (ci + 2 < NC){
            const int nb = (ci + 2) % 3;
            load_tile(ci + 2, sb + (uint32_t)nb * TB);
        }
        const uint32_t cur = sb + (uint32_t)(ci % 3) * TB;

#pragma unroll
        for (int s = 0; s < BK / 16; s++){
            uint32_t a[2][4];
#pragma unroll
            for (int i = 0; i < 2; i++)
                ldsm4(a[i][0], a[i][1], a[i][2], a[i][3], cur + aOff + i * (16 * PITCH) + s * 32);
            uint32_t b0, b1, b2, b3, b4, b5, b6, b7;
            ldsm4(b0, b1, b2, b3, cur + bOff + s * 32);
            ldsm4(b4, b5, b6, b7, cur + bOff + 16 * PITCH + s * 32);
#pragma unroll
            for (int i = 0; i < 2; i++){
                mma16816(acc[i][0], a[i][0], a[i][1], a[i][2], a[i][3], b0, b1);
                mma16816(acc[i][1], a[i][0], a[i][1], a[i][2], a[i][3], b2, b3);
                mma16816(acc[i][2], a[i][0], a[i][1], a[i][2], a[i][3], b4, b5);
                mma16816(acc[i][3], a[i][0], a[i][1], a[i][2], a[i][3], b6, b7);
            }
        }
    }

    const int t4 = lane >> 2, tp = (lane & 3) * 2;
#pragma unroll
    for (int i = 0; i < 2; i++){
#pragma unroll
        for (int j = 0; j < 4; j++){
            const int col = bn + wn * 32 + j * 8 + tp;
            if (col >= N) continue;
            const int row0 = bm + wm * 32 + i * 16 + t4;
            float v0 = acc[i][j][0], v1 = acc[i][j][1];
            float v2 = acc[i][j][2], v3 = acc[i][j][3];
            if (EPI >= 1 && EPI <= 4){
                const float bb0 = bias[col], bb1 = bias[col + 1];
                v0 += bb0; v1 += bb1; v2 += bb0; v3 += bb1;
            }
            if (EPI == 5){
                const float* bp = (col < 512) ? bias : (col < 1024) ? (bias_b - 512) : (bias_c - 1024);
                const float bb0 = bp[col], bb1 = bp[col + 1];
                v0 += bb0; v1 += bb1; v2 += bb0; v3 += bb1;
            }
            if (EPI == 2){ v0 = softplus_f(v0); v1 = softplus_f(v1); v2 = softplus_f(v2); v3 = softplus_f(v3); }
            if (EPI == 3){ v0 = gelu_f(v0); v1 = gelu_f(v1); v2 = gelu_f(v2); v3 = gelu_f(v3); }
            if (EPI == 4){
                v0 += res[(size_t)row0 * N + col];
                v1 += res[(size_t)row0 * N + col + 1];
                v2 += res[(size_t)(row0 + 8) * N + col];
                v3 += res[(size_t)(row0 + 8) * N + col + 1];
            }
            if (EPI == 6){
                if (col < 1536){
                    const float* bp = (col < 512) ? bias : (col < 1024) ? (bias_b - 512) : (bias_c - 1024);
                    const float bb0 = bp[col], bb1 = bp[col + 1];
                    const float q0 = v0 + bb0, q1 = v1 + bb1;
                    const float q2 = v2 + bb0, q3 = v3 + bb1;
                    const size_t r0 = (size_t)row0 * 3072, r1 = (size_t)(row0 + 8) * 3072;
                    *(__nv_bfloat162*)&C3[r0 + col]        = hi2(q0, q1);
                    *(__nv_bfloat162*)&C3[r0 + 1536 + col] = lo2(q0, q1);
                    *(__nv_bfloat162*)&C3[r1 + col]        = hi2(q2, q3);
                    *(__nv_bfloat162*)&C3[r1 + 1536 + col] = lo2(q2, q3);
                } else {
                    const int cc = col - 1536;
                    *(float2*)&C[(size_t)row0 * 2048 + cc]       = make_float2(v0, v1);
                    *(float2*)&C[(size_t)(row0 + 8) * 2048 + cc] = make_float2(v2, v3);
                }
                continue;
            }
            if (OUT3){
                const size_t r0 = (size_t)row0 * (2 * N), r1 = (size_t)(row0 + 8) * (2 * N);
                *(__nv_bfloat162*)&C3[r0 + col]     = hi2(v0, v1);
                *(__nv_bfloat162*)&C3[r0 + N + col] = lo2(v0, v1);
                *(__nv_bfloat162*)&C3[r1 + col]     = hi2(v2, v3);
                *(__nv_bfloat162*)&C3[r1 + N + col] = lo2(v2, v3);
            } else {
                *(float2*)&C[(size_t)row0 * N + col]       = make_float2(v0, v1);
                *(float2*)&C[(size_t)(row0 + 8) * N + col] = make_float2(v2, v3);
            }
        }
    }
}
#define GEMM_SMEM32 (3 * 256 * 80)
#define GEMM_SMEM64 (3 * 256 * 144)

// =====================================================================
// Flash attention v3: reads bf16 [hi|lo] QKV (pitch 3072) via cp.async.
// Register-resident softmax/P (unchanged math from v2).
// =====================================================================
#define FQ 0
#define FK 34816
#define FV 52224
#define FMSK 70656
#define FLASH_SMEM 70912

__global__ __launch_bounds__(256, 2) void flash_mma(
    const bf16* __restrict__ QKV2, const unsigned char* __restrict__ mask,
    bf16* __restrict__ AO2)
{
    extern __shared__ char sm[];
    const uint32_t sb = smem_u32(sm);
    float* mskf = (float*)(sm + FMSK);
    const int tid = threadIdx.x;
    const int w = tid >> 5, lane = tid & 31;
    const int t4 = lane >> 2, qq = lane & 3;
    const int bh = blockIdx.y, b = bh >> 3, h = bh & 7;
    const int q0 = blockIdx.x * 128;
    const size_t basebl = (size_t)b * cL;

    // Q load (once): copy hi/lo rows directly
    for (int idx = tid; idx < 2048; idx += 256){
        const int row = idx >> 4, c = idx & 15;
        const size_t g = (basebl + q0 + row) * 3072 + h * 64;
        if (c < 8) cp16(sb + FQ + row * 272 + c * 16, &QKV2[g + c * 8]);
        else       cp16(sb + FQ + row * 272 + 128 + (c - 8) * 16, &QKV2[g + 1536 + (c - 8) * 8]);
    }
    asm volatile("cp.async.commit_group;" ::: "memory");

    float m0 = -1e30f, m1 = -1e30f, l0 = 0.f, l1 = 0.f;
    float o[8][4];
#pragma unroll
    for (int nt = 0; nt < 8; nt++)
#pragma unroll
        for (int e = 0; e < 4; e++) o[nt][e] = 0.f;

    for (int jt = 0; jt < cL / 64; jt++){
        __syncthreads();
        for (int idx = tid; idx < 2048; idx += 256){
            if (idx < 1024){
                const int row = idx >> 4, c = idx & 15;
                const size_t g = (basebl + jt * 64 + row) * 3072 + 512 + h * 64;
                if (c < 8) cp16(sb + FK + row * 272 + c * 16, &QKV2[g + c * 8]);
                else       cp16(sb + FK + row * 272 + 128 + (c - 8) * 16, &QKV2[g + 1024 + (c - 8) * 8]);
            } else {
                const int i2 = idx - 1024;
                const int row = i2 >> 4, c = i2 & 15;
                const size_t g = (basebl + jt * 64 + row) * 3072 + 1024 + h * 64;
                if (c < 8) cp16(sb + FV + row * 144 + c * 16, &QKV2[g + c * 8]);
                else       cp16(sb + FV + (64 + row) * 144 + (c - 8) * 16, &QKV2[g + 512 + (c - 8) * 8]);
            }
        }
        asm volatile("cp.async.commit_group;" ::: "memory");
        if (tid < 64) mskf[tid] = mask[b * cL + jt * 64 + tid] ? -1e30f : 0.0f;
        asm volatile("cp.async.wait_group 0;" ::: "memory");
        __syncthreads();

        float sacc[8][4];
#pragma unroll
        for (int nt = 0; nt < 8; nt++)
#pragma unroll
            for (int e = 0; e < 4; e++) sacc[nt][e] = 0.f;

#pragma unroll
        for (int s = 0; s < 12; s++){
            const int ab = (s < 4) ? s * 32 : (s < 8) ? 128 + (s - 4) * 32 : (s - 8) * 32;
            const int bb = (s < 8) ? (s & 3) * 32 : 128 + (s - 8) * 32;
            uint32_t a0, a1, a2, a3;
            ldsm4(a0, a1, a2, a3, sb + FQ + (w * 16 + (lane & 15)) * 272 + ab + (lane >> 4) * 16);
#pragma unroll
            for (int kc = 0; kc < 4; kc++){
                uint32_t b0, b1, b2, b3;
                ldsm4(b0, b1, b2, b3,
                      sb + FK + (kc * 16 + (lane & 7) + ((lane & 16) ? 8 : 0)) * 272 + bb + ((lane >> 3) & 1) * 16);
                mma16816(sacc[2 * kc],     a0, a1, a2, a3, b0, b1);
                mma16816(sacc[2 * kc + 1], a0, a1, a2, a3, b2, b3);
            }
        }

        float mx0 = -1e30f, mx1 = -1e30f;
#pragma unroll
        for (int nt = 0; nt < 8; nt++){
            const float2 mk = *(const float2*)&mskf[nt * 8 + qq * 2];
            sacc[nt][0] = sacc[nt][0] * 0.125f + mk.x;
            sacc[nt][1] = sacc[nt][1] * 0.125f + mk.y;
            sacc[nt][2] = sacc[nt][2] * 0.125f + mk.x;
            sacc[nt][3] = sacc[nt][3] * 0.125f + mk.y;
            mx0 = fmaxf(mx0, fmaxf(sacc[nt][0], sacc[nt][1]));
            mx1 = fmaxf(mx1, fmaxf(sacc[nt][2], sacc[nt][3]));
        }
        mx0 = fmaxf(mx0, __shfl_xor_sync(0xffffffffu, mx0, 1));
        mx0 = fmaxf(mx0, __shfl_xor_sync(0xffffffffu, mx0, 2));
        mx1 = fmaxf(mx1, __shfl_xor_sync(0xffffffffu, mx1, 1));
        mx1 = fmaxf(mx1, __shfl_xor_sync(0xffffffffu, mx1, 2));
        const float mn0 = fmaxf(m0, mx0), mn1 = fmaxf(m1, mx1);
        const float fac0 = __expf(m0 - mn0), fac1 = __expf(m1 - mn1);
        m0 = mn0; m1 = mn1;
        float sum0 = 0.f, sum1 = 0.f;
#pragma unroll
        for (int nt = 0; nt < 8; nt++){
            sacc[nt][0] = __expf(sacc[nt][0] - mn0);
            sacc[nt][1] = __expf(sacc[nt][1] - mn0);
            sacc[nt][2] = __expf(sacc[nt][2] - mn1);
            sacc[nt][3] = __expf(sacc[nt][3] - mn1);
            sum0 += sacc[nt][0] + sacc[nt][1];
            sum1 += sacc[nt][2] + sacc[nt][3];
        }
        sum0 += __shfl_xor_sync(0xffffffffu, sum0, 1);
        sum0 += __shfl_xor_sync(0xffffffffu, sum0, 2);
        sum1 += __shfl_xor_sync(0xffffffffu, sum1, 1);
        sum1 += __shfl_xor_sync(0xffffffffu, sum1, 2);
        l0 = l0 * fac0 + sum0;
        l1 = l1 * fac1 + sum1;
#pragma unroll
        for (int nt = 0; nt < 8; nt++){
            o[nt][0] *= fac0; o[nt][1] *= fac0;
            o[nt][2] *= fac1; o[nt][3] *= fac1;
        }

        uint32_t Ph[4][4], Pl[4][4];
#pragma unroll
        for (int kk = 0; kk < 4; kk++){
            Ph[kk][0] = hi2u(sacc[2*kk][0],   sacc[2*kk][1]);
            Ph[kk][1] = hi2u(sacc[2*kk][2],   sacc[2*kk][3]);
            Ph[kk][2] = hi2u(sacc[2*kk+1][0], sacc[2*kk+1][1]);
            Ph[kk][3] = hi2u(sacc[2*kk+1][2], sacc[2*kk+1][3]);
            Pl[kk][0] = lo2u(sacc[2*kk][0],   sacc[2*kk][1]);
            Pl[kk][1] = lo2u(sacc[2*kk][2],   sacc[2*kk][3]);
            Pl[kk][2] = lo2u(sacc[2*kk+1][0], sacc[2*kk+1][1]);
            Pl[kk][3] = lo2u(sacc[2*kk+1][2], sacc[2*kk+1][3]);
        }

#pragma unroll
        for (int s = 0; s < 12; s++){
            const uint32_t* af = (s < 4) ? Ph[s] : (s < 8) ? Pl[s - 4] : Ph[s - 8];
            const int vr = (s < 8) ? (s & 3) * 16 : 64 + (s - 8) * 16;
#pragma unroll
            for (int nb = 0; nb < 4; nb++){
                uint32_t v0, v1, v2, v3;
                ldsm4t(v0, v1, v2, v3,
                       sb + FV + (vr + (lane & 15)) * 144 + (nb * 16 + ((lane & 16) ? 8 : 0)) * 2);
                mma16816(o[2 * nb],     af[0], af[1], af[2], af[3], v0, v1);
                mma16816(o[2 * nb + 1], af[0], af[1], af[2], af[3], v2, v3);
            }
        }
    }

    const float i0 = 1.0f / l0, i1 = 1.0f / l1;
    const size_t gA = (basebl + q0 + w * 16 + t4) * 1024;
    const size_t gB = gA + 8 * 1024;
#pragma unroll
    for (int nt = 0; nt < 8; nt++){
        const float a0 = o[nt][0] * i0, a1 = o[nt][1] * i0;
        const float a2 = o[nt][2] * i1, a3 = o[nt][3] * i1;
        const int col = h * 64 + nt * 8 + qq * 2;
        *(__nv_bfloat162*)&AO2[gA + col]       = hi2(a0, a1);
        *(__nv_bfloat162*)&AO2[gA + 512 + col] = lo2(a0, a1);
        *(__nv_bfloat162*)&AO2[gB + col]       = hi2(a2, a3);
        *(__nv_bfloat162*)&AO2[gB + 512 + col] = lo2(a2, a3);
    }
}

// =====================================================================
// conv_silu v2 (unchanged from R13): 4 timesteps x 4 channels
// =====================================================================
__global__ __launch_bounds__(256) void conv_silu(
    const float* __restrict__ xz, const float* __restrict__ cw,
    const float* __restrict__ cb, float* __restrict__ u, bf16* __restrict__ u2)
{
    const long idx = (long)blockIdx.x * 256 + threadIdx.x;
    const int c = (int)(idx & 255) * 4;
    const int mg = (int)(idx >> 8);
    const int b = mg / (cL / 4), lg = mg % (cL / 4);
    const int l0 = lg * 4;
    const size_t rowb = (size_t)(b * cL + l0) * (2 * cDI) + c;

    F4U w0, w1, w2, w3, bias;
    w0.f4 = *(const float4*)&cw[c * 4];
    w1.f4 = *(const float4*)&cw[(c + 1) * 4];
    w2.f4 = *(const float4*)&cw[(c + 2) * 4];
    w3.f4 = *(const float4*)&cw[(c + 3) * 4];
    bias.f4 = *(const float4*)&cb[c];

    F4U xv[7];
#pragma unroll
    for (int i = 0; i < 7; i++){
        const int l = l0 + i - 3;
        if (l >= 0) xv[i].f4 = *(const float4*)&xz[rowb + (size_t)(i - 3) * (2 * cDI)];
        else        xv[i].f4 = make_float4(0.f, 0.f, 0.f, 0.f);
    }

#pragma unroll
    for (int j = 0; j < 4; j++){
        F4U acc; acc.f4 = bias.f4;
#pragma unroll
        for (int k = 0; k < 4; k++){
            acc.f[0] += xv[j + k].f[0] * w0.f[k];
            acc.f[1] += xv[j + k].f[1] * w1.f[k];
            acc.f[2] += xv[j + k].f[2] * w2.f[k];
            acc.f[3] += xv[j + k].f[3] * w3.f[k];
        }
#pragma unroll
        for (int e = 0; e < 4; e++) acc.f[e] = acc.f[e] / (1.0f + __expf(-acc.f[e]));
        const int m = b * cL + l0 + j;
        *(float4*)&u[(size_t)m * cDI + c] = acc.f4;
        const size_t r2 = (size_t)m * 2048;
        __nv_bfloat162 hh[2] = { hi2(acc.f[0], acc.f[1]), hi2(acc.f[2], acc.f[3]) };
        __nv_bfloat162 ll[2] = { lo2(acc.f[0], acc.f[1]), lo2(acc.f[2], acc.f[3]) };
        *(uint2*)&u2[r2 + c]        = *(uint2*)hh;
        *(uint2*)&u2[r2 + 1024 + c] = *(uint2*)ll;
    }
}

// =====================================================================
// Selective scan v4: depth-8 smem staging, 256 thr = 8 warps = 16 d.
// 2 bufs x 8 steps x 176 floats (B64 C64 dt16 u16 z16); 1 sync / 8 steps.
// =====================================================================
__global__ __launch_bounds__(256) void mamba_scan(
    const float* __restrict__ delta, const float* __restrict__ u,
    const float* __restrict__ xdbc, const float* __restrict__ xz,
    const float* __restrict__ A_log, const float* __restrict__ Dssm,
    bf16* __restrict__ y2)
{
    __shared__ float sbuf[2][8][176];
    const int tid = threadIdx.x;
    const int warp = tid >> 5, lane = tid & 31;
    const int half = lane >> 4, sl = lane & 15;
    const int d0 = blockIdx.x * 16;
    const int dl = warp * 2 + half;
    const int d = d0 + dl;
    const int b = blockIdx.y;
    float a[4], hh[4];
#pragma unroll
    for (int k = 0; k < 4; k++){
        a[k] = -__expf(A_log[d * cS + sl * 4 + k]);
        hh[k] = 0.f;
    }
    const float Dd = Dssm[d];
    const size_t base = (size_t)b * cL;
    const uint32_t sbase = smem_u32(sbuf);

    auto stage = [&](int g, int buf){
        const int t0 = g * 8;
#pragma unroll
        for (int cc = 0; cc < 2; cc++){
            const int i = tid + cc * 256;
            if (i < 352){
                const int step = i / 44, within = i % 44;
                const size_t m = base + t0 + step;
                const float* src;
                if (within < 16)      src = &xdbc[m * 160 + 32 + within * 4];
                else if (within < 32) src = &xdbc[m * 160 + 96 + (within - 16) * 4];
                else if (within < 36) src = &delta[m * cDI + d0 + (within - 32) * 4];
                else if (within < 40) src = &u[m * cDI + d0 + (within - 36) * 4];
                else                  src = &xz[m * (2 * cDI) + cDI + d0 + (within - 40) * 4];
                cp16(sbase + (uint32_t)buf * 5632 + step * 704 + within * 16, src);
            }
        }
        asm volatile("cp.async.commit_group;" ::: "memory");
    };

    stage(0, 0);
    asm volatile("cp.async.wait_group 0;" ::: "memory");
    __syncthreads();

    const int G = cL / 8;
    for (int g = 0; g < G; g++){
        if (g + 1 < G) stage(g + 1, (g + 1) & 1);
        const float (*grp)[176] = sbuf[g & 1];
#pragma unroll
        for (int s = 0; s < 8; s++){
            const float* slab = grp[s];
            const float dt = slab[128 + dl];
            const float uu = slab[144 + dl];
            F4U Bv, Cv;
            Bv.f4 = *(const float4*)&slab[sl * 4];
            Cv.f4 = *(const float4*)&slab[64 + sl * 4];
            const float du = dt * uu;
            float p = 0.f;
#pragma unroll
            for (int k = 0; k < 4; k++){
                hh[k] = hh[k] * __expf(dt * a[k]) + du * Bv.f[k];
                p += hh[k] * Cv.f[k];
            }
            p += __shfl_xor_sync(0xffffffffu, p, 8);
            p += __shfl_xor_sync(0xffffffffu, p, 4);
            p += __shfl_xor_sync(0xffffffffu, p, 2);
            p += __shfl_xor_sync(0xffffffffu, p, 1);
            if (sl == 0){
                const float z = slab[160 + dl];
                float yv = p + uu * Dd;
                yv *= z / (1.0f + __expf(-z));
                const size_t r2 = (base + g * 8 + s) * 2048;
                y2[r2 + d]        = hi_bf(yv);
                y2[r2 + 1024 + d] = lo_bf(yv);
            }
        }
        asm volatile("cp.async.wait_group 0;" ::: "memory");
        __syncthreads();
    }
}

// =====================================================================
// Fused residual + LN1 + LN2
// =====================================================================
__device__ __forceinline__ float blockSum256(float v, float* red){
#pragma unroll
    for (int off = 16; off > 0; off >>= 1) v += __shfl_xor_sync(0xffffffffu, v, off);
    if ((threadIdx.x & 31) == 0) red[threadIdx.x >> 5] = v;
    __syncthreads();
    const float s = red[0]+red[1]+red[2]+red[3]+red[4]+red[5]+red[6]+red[7];
    __syncthreads();
    return s;
}

__global__ __launch_bounds__(256) void ln_fuse(
    const float* __restrict__ xf, const float* __restrict__ attn, const float* __restrict__ mamba,
    const float* __restrict__ g1, const float* __restrict__ b1,
    const float* __restrict__ g2, const float* __restrict__ b2,
    float* __restrict__ h, bf16* __restrict__ hn2)
{
    __shared__ float red[8];
    const size_t m = blockIdx.x;
    const int t = threadIdx.x * 2;
    const size_t r = m * cD;
    const float2 xv = *(const float2*)&xf[r + t];
    const float2 av = *(const float2*)&attn[r + t];
    const float2 mv = *(const float2*)&mamba[r + t];
    float v0 = xv.x + av.x + mv.x;
    float v1 = xv.y + av.y + mv.y;

    const float mean = blockSum256(v0 + v1, red) * (1.0f / cD);
    const float d0 = v0 - mean, d1 = v1 - mean;
    const float var = blockSum256(d0 * d0 + d1 * d1, red) * (1.0f / cD);
    const float inv = rsqrtf(var + 1e-5f);
    const float2 g1v = *(const float2*)&g1[t];
    const float2 b1v = *(const float2*)&b1[t];
    const float h0 = d0 * inv * g1v.x + b1v.x;
    const float h1 = d1 * inv * g1v.y + b1v.y;
    *(float2*)&h[r + t] = make_float2(h0, h1);

    const float mean2 = blockSum256(h0 + h1, red) * (1.0f / cD);
    const float e0 = h0 - mean2, e1 = h1 - mean2;
    const float var2 = blockSum256(e0 * e0 + e1 * e1, red) * (1.0f / cD);
    const float inv2 = rsqrtf(var2 + 1e-6f);
    const float2 g2v = *(const float2*)&g2[t];
    const float2 b2v = *(const float2*)&b2[t];
    const float n0 = e0 * inv2 * g2v.x + b2v.x;
    const float n1 = e1 * inv2 * g2v.y + b2v.y;
    const size_t r2 = m * 1024;
    *(__nv_bfloat162*)&hn2[r2 + t]       = hi2(n0, n1);
    *(__nv_bfloat162*)&hn2[r2 + 512 + t] = lo2(n0, n1);
}

// =====================================================================
// Launch
// =====================================================================
static inline int sgrid2(long rows, int K){
    return (int)((rows * (K >> 2) + 255) / 256);
}

extern "C" void kernel_launch(void* const* d_in, const int* in_sizes, int n_in,
                              void* d_out, int out_size)
{
    (void)in_sizes; (void)n_in; (void)out_size;
    const float* x      = (const float*)d_in[0];
    const unsigned char* mask = (const unsigned char*)d_in[1];
    const float* Wq = (const float*)d_in[2];  const float* bq = (const float*)d_in[3];
    const float* Wk = (const float*)d_in[4];  const float* bk = (const float*)d_in[5];
    const float* Wv = (const float*)d_in[6];  const float* bv = (const float*)d_in[7];
    const float* Wo = (const float*)d_in[8];  const float* bo = (const float*)d_in[9];
    const float* in_w   = (const float*)d_in[10];
    const float* conv_w = (const float*)d_in[11];
    const float* conv_b = (const float*)d_in[12];
    const float* xproj_w= (const float*)d_in[13];
    const float* dt_w   = (const float*)d_in[14];
    const float* dt_b   = (const float*)d_in[15];
    const float* A_log  = (const float*)d_in[16];
    const float* Dssm   = (const float*)d_in[17];
    const float* outp_w = (const float*)d_in[18];
    const float* ln1g   = (const float*)d_in[19];
    const float* ln1b   = (const float*)d_in[20];
    const float* fw1    = (const float*)d_in[21];
    const float* fb1    = (const float*)d_in[22];
    const float* fw2    = (const float*)d_in[23];
    const float* fb2    = (const float*)d_in[24];
    const float* ln2g   = (const float*)d_in[25];
    const float* ln2b   = (const float*)d_in[26];
    float* out = (float*)d_out;

    float *attn,*xz,*u,*xdbc,*dlt,*mmb,*h;
    cudaGetSymbolAddress((void**)&attn, g_attn);
    cudaGetSymbolAddress((void**)&xz,   g_xz);
    cudaGetSymbolAddress((void**)&u,    g_u);
    cudaGetSymbolAddress((void**)&xdbc, g_xdbc);
    cudaGetSymbolAddress((void**)&dlt,  g_dlt);
    cudaGetSymbolAddress((void**)&mmb,  g_mmb);
    cudaGetSymbolAddress((void**)&h,    g_h);

    bf16 *pqkv2,*px2,*pao2,*pu2,*pxdbc2,*py2,*phn2,*pff12;
    bf16 *pwqi,*pwo,*pwxp,*pwdt,*pwout,*pwf1,*pwf2;
    cudaGetSymbolAddress((void**)&pqkv2, g_qkv2);
    cudaGetSymbolAddress((void**)&px2,   gx2);
    cudaGetSymbolAddress((void**)&pao2,  gao2);
    cudaGetSymbolAddress((void**)&pu2,   gu2);
    cudaGetSymbolAddress((void**)&pxdbc2,gxdbc2);
    cudaGetSymbolAddress((void**)&py2,   gy2);
    cudaGetSymbolAddress((void**)&phn2,  ghn2);
    cudaGetSymbolAddress((void**)&pff12, gff12);
    cudaGetSymbolAddress((void**)&pwqi,  wqi2);
    cudaGetSymbolAddress((void**)&pwo,   wo2);
    cudaGetSymbolAddress((void**)&pwxp,  wxp2);
    cudaGetSymbolAddress((void**)&pwdt,  wdt2);
    cudaGetSymbolAddress((void**)&pwout, wout2);
    cudaGetSymbolAddress((void**)&pwf1,  wff12);
    cudaGetSymbolAddress((void**)&pwf2,  wff22);

    cudaFuncSetAttribute(flash_mma, cudaFuncAttributeMaxDynamicSharedMemorySize, FLASH_SMEM);
    cudaFuncSetAttribute(hmma_gemm<0,false,64>, cudaFuncAttributeMaxDynamicSharedMemorySize, GEMM_SMEM64);
    cudaFuncSetAttribute(hmma_gemm<1,false,64>, cudaFuncAttributeMaxDynamicSharedMemorySize, GEMM_SMEM64);
    cudaFuncSetAttribute(hmma_gemm<3,true,64>,  cudaFuncAttributeMaxDynamicSharedMemorySize, GEMM_SMEM64);
    cudaFuncSetAttribute(hmma_gemm<4,false,64>, cudaFuncAttributeMaxDynamicSharedMemorySize, GEMM_SMEM64);
    cudaFuncSetAttribute(hmma_gemm<6,false,64>, cudaFuncAttributeMaxDynamicSharedMemorySize, GEMM_SMEM64);
    cudaFuncSetAttribute(hmma_gemm<2,false,32>, cudaFuncAttributeMaxDynamicSharedMemorySize, GEMM_SMEM32);

    // ---- fused weight-split table ----
    WTab tab;
    long base = 0;
    auto add = [&](int i, const float* src, bf16* dst, int K, long rows){
        tab.e[i] = {src, dst, K, rows, base};
        base += rows * (K >> 2);
    };
    add(0, Wq,      pwqi,                512,  512);
    add(1, Wk,      pwqi + 512 * 1024,   512,  512);
    add(2, Wv,      pwqi + 1024 * 1024,  512,  512);
    add(3, in_w,    pwqi + 1536 * 1024,  512,  2048);
    add(4, Wo,      pwo,                 512,  512);
    add(5, xproj_w, pwxp,                1024, 160);
    add(6, dt_w,    pwdt,                32,   1024);
    add(7, outp_w,  pwout,               1024, 512);
    add(8, fw1,     pwf1,                512,  2048);
    add(9, fw2,     pwf2,                2048, 512);
    const int wgrid = (int)((base + 255) / 256);

    cudaStream_t s0 = 0, sB = g_sh.sB;

    split2_wgt_all<<<wgrid, 256, 0, s0>>>(tab);
    split2<<<sgrid2(cM, 512), 256, 0, s0>>>(x, 512, 512, px2, cM);

    // merged QKV + in_proj GEMM (N=3584): QKV -> bf16 split, in_proj -> fp32 xz
    hmma_gemm<6,false,64><<<dim3(28, 72), 512, GEMM_SMEM64, s0>>>(px2, pwqi, 512, bq, bk, bv, nullptr, xz, pqkv2, 3584);

    cudaEventRecord(g_sh.evRoot, s0);
    cudaStreamWaitEvent(sB, g_sh.evRoot, 0);

    // attention branch on s0 (flash at submission slot 3 = ncu target)
    flash_mma<<<dim3(cL / 128, cB * 8), 256, FLASH_SMEM, s0>>>(pqkv2, mask, pao2);
    hmma_gemm<1,false,64><<<dim3(4, 72), 512, GEMM_SMEM64, s0>>>(pao2, pwo, 512, bo, nullptr, nullptr, nullptr, attn, nullptr, 512);

    // mamba branch on sB
    conv_silu<<<(cM / 4), 256, 0, sB>>>(xz, conv_w, conv_b, u, pu2);
    hmma_gemm<0,false,64><<<dim3(2, 72), 512, GEMM_SMEM64, sB>>>(pu2, pwxp, 1024, nullptr, nullptr, nullptr, nullptr, xdbc, nullptr, 160);
    split2<<<sgrid2(cM, 32), 256, 0, sB>>>(xdbc, 160, 32, pxdbc2, cM);
    hmma_gemm<2,false,32><<<dim3(8, 72), 512, GEMM_SMEM32, sB>>>(pxdbc2, pwdt, 32, dt_b, nullptr, nullptr, nullptr, dlt, nullptr, 1024);
    mamba_scan<<<dim3(cDI / 16, cB), 256, 0, sB>>>(dlt, u, xdbc, xz, A_log, Dssm, py2);
    hmma_gemm<0,false,64><<<dim3(4, 72), 512, GEMM_SMEM64, sB>>>(py2, pwout, 1024, nullptr, nullptr, nullptr, nullptr, mmb, nullptr, 512);
    cudaEventRecord(g_sh.evB, sB);

    cudaStreamWaitEvent(s0, g_sh.evB, 0);
    ln_fuse<<<cM, 256, 0, s0>>>(x, attn, mmb, ln1g, ln1b, ln2g, ln2b, h, phn2);
    hmma_gemm<3,true,64><<<dim3(16, 72), 512, GEMM_SMEM64, s0>>>(phn2, pwf1, 512, fb1, nullptr, nullptr, nullptr, nullptr, pff12, 2048);
    hmma_gemm<4,false,64><<<dim3(4, 72), 512, GEMM_SMEM64, s0>>>(pff12, pwf2, 2048, fb2, nullptr, nullptr, h, out, nullptr, 512);
}